// round 12
// baseline (speedup 1.0000x reference)
#include <cuda_runtime.h>
#include <cuda_bf16.h>
#include <cstdint>
#include <math.h>
#include <math_constants.h>

// Problem constants
#define BB 32
#define SS 512
#define DD 256
#define HH 8
#define DHH 32
#define NROWS (BB*SS)

// Scratch (__device__ globals; allocation is banned)
__device__ uint16_t g_qkh[(size_t)NROWS * 512];   // bf16 hi: [row][0:256)=q, [256:512)=k
__device__ uint16_t g_qkl[(size_t)NROWS * 512];   // bf16 lo
__device__ float    g_v[(size_t)NROWS * 256];     // v fp32
__device__ float    g_tmp[(size_t)NROWS * 256];   // avg @ v result

// ---------------------------------------------------------------------------
// bf16 split + pack helpers (3xBF16 fp32 emulation)
// ---------------------------------------------------------------------------
__device__ __forceinline__ void splitpk(float x, float y, uint32_t& h, uint32_t& l) {
    __nv_bfloat16 hx = __float2bfloat16(x), hy = __float2bfloat16(y);
    float rx = x - __bfloat162float(hx);
    float ry = y - __bfloat162float(hy);
    __nv_bfloat16 lx = __float2bfloat16(rx), ly = __float2bfloat16(ry);
    h = (uint32_t)__bfloat16_as_ushort(hx) | ((uint32_t)__bfloat16_as_ushort(hy) << 16);
    l = (uint32_t)__bfloat16_as_ushort(lx) | ((uint32_t)__bfloat16_as_ushort(ly) << 16);
}

__device__ __forceinline__ uint32_t cvta_s(const void* p) {
    return (uint32_t)__cvta_generic_to_shared(p);
}

__device__ __forceinline__ void ldmx4(uint32_t r[4], uint32_t addr) {
    asm volatile("ldmatrix.sync.aligned.m8n8.x4.shared.b16 {%0,%1,%2,%3}, [%4];"
                 : "=r"(r[0]), "=r"(r[1]), "=r"(r[2]), "=r"(r[3]) : "r"(addr));
}
__device__ __forceinline__ void ldmx4t(uint32_t r[4], uint32_t addr) {
    asm volatile("ldmatrix.sync.aligned.m8n8.x4.trans.shared.b16 {%0,%1,%2,%3}, [%4];"
                 : "=r"(r[0]), "=r"(r[1]), "=r"(r[2]), "=r"(r[3]) : "r"(addr));
}

__device__ __forceinline__ void mma16816(float c[4], const uint32_t a[4],
                                         uint32_t b0, uint32_t b1) {
    asm volatile(
        "mma.sync.aligned.m16n8k16.row.col.f32.bf16.bf16.f32 "
        "{%0,%1,%2,%3}, {%4,%5,%6,%7}, {%8,%9}, {%0,%1,%2,%3};"
        : "+f"(c[0]), "+f"(c[1]), "+f"(c[2]), "+f"(c[3])
        : "r"(a[0]), "r"(a[1]), "r"(a[2]), "r"(a[3]), "r"(b0), "r"(b1));
}

// ---------------------------------------------------------------------------
// Tile strides
// ---------------------------------------------------------------------------
#define AT_STR 40    // K-major tiles: 32 k + 8 pad
#define BN_STR 136   // NN B tile [k][n]: 128 n + 8 pad

#define TN_TILE_B  (128 * AT_STR * 2)            // 10240
#define TN_BUF_B   (4 * TN_TILE_B)               // 40960
#define TN_SMEM_B  (2 * TN_BUF_B)                // 81920

#define NN_BT_B    (32 * BN_STR * 2)             // 8704
#define NN_BUF_B   (2 * TN_TILE_B + 2 * NN_BT_B) // 37888
#define NN_SMEM_B  (2 * NN_BUF_B)                // 75776

// Stage a 128x32 fp32 K-contig tile -> hi/lo bf16 smem, 512 threads.
// thread: row = tid>>2, kh = (tid&3)*8; f[2] = 8 floats preloaded.
__device__ __forceinline__ void stage_tn512(uint16_t* hi, uint16_t* lo,
                                            const float4 f[2], int tid) {
    int row = tid >> 2, kh = (tid & 3) * 8;
    uint4 H, L;
    splitpk(f[0].x, f[0].y, H.x, L.x); splitpk(f[0].z, f[0].w, H.y, L.y);
    splitpk(f[1].x, f[1].y, H.z, L.z); splitpk(f[1].z, f[1].w, H.w, L.w);
    *(uint4*)(hi + row * AT_STR + kh) = H;
    *(uint4*)(lo + row * AT_STR + kh) = L;
}

// Stage a 32x128 fp32 N-contig tile -> hi/lo bf16 smem [k][n], 512 threads.
// thread: k = tid>>4, n8 = (tid&15)*8; f[2] = 8 floats preloaded.
__device__ __forceinline__ void stage_nn_b512(uint16_t* hi, uint16_t* lo,
                                              const float4 f[2], int tid) {
    int k = tid >> 4, n8 = (tid & 15) * 8;
    uint4 H, L;
    splitpk(f[0].x, f[0].y, H.x, L.x); splitpk(f[0].z, f[0].w, H.y, L.y);
    splitpk(f[1].x, f[1].y, H.z, L.z); splitpk(f[1].z, f[1].w, H.w, L.w);
    *(uint4*)(hi + k * BN_STR + n8) = H;
    *(uint4*)(lo + k * BN_STR + n8) = L;
}

// Warp-level K-chunk compute: 32x32 warp tile (mi<2), 3-pass split.
template<bool TRANSB>
__device__ __forceinline__ void compute_chunk(
    float c[2][4][4],
    const uint16_t* sAhi, const uint16_t* sAlo,
    const uint16_t* sBhi, const uint16_t* sBlo,
    int lane, int mrow0, int ncol0)
{
    const int lr = lane & 7, lg = lane >> 3;
#pragma unroll
    for (int k16 = 0; k16 < 32; k16 += 16) {
        uint32_t ah[2][4], al[2][4];
        uint32_t aoff = (uint32_t)(((mrow0 + (lane & 15)) * AT_STR + k16 + ((lane >> 4) << 3)) * 2);
#pragma unroll
        for (int mi = 0; mi < 2; ++mi) {
            ldmx4(ah[mi], cvta_s(sAhi) + aoff + mi * (16 * AT_STR * 2));
            ldmx4(al[mi], cvta_s(sAlo) + aoff + mi * (16 * AT_STR * 2));
        }
        uint32_t bh[2][4], bl[2][4];
#pragma unroll
        for (int nb = 0; nb < 2; ++nb) {
            uint32_t boff;
            if (TRANSB) {
                boff = (uint32_t)(((k16 + lr + ((lg & 1) << 3)) * BN_STR
                                   + ncol0 + nb * 16 + ((lg & 2) << 2)) * 2);
                ldmx4t(bh[nb], cvta_s(sBhi) + boff);
                ldmx4t(bl[nb], cvta_s(sBlo) + boff);
            } else {
                boff = (uint32_t)(((ncol0 + nb * 16 + lr + ((lg & 2) << 2)) * AT_STR
                                   + k16 + ((lg & 1) << 3)) * 2);
                ldmx4(bh[nb], cvta_s(sBhi) + boff);
                ldmx4(bl[nb], cvta_s(sBlo) + boff);
            }
        }
#pragma unroll
        for (int mi = 0; mi < 2; ++mi)
#pragma unroll
            for (int nb = 0; nb < 2; ++nb)
#pragma unroll
                for (int half = 0; half < 2; ++half) {
                    float* cc = c[mi][nb * 2 + half];
                    mma16816(cc, ah[mi], bh[nb][half * 2], bh[nb][half * 2 + 1]);
                    mma16816(cc, ah[mi], bl[nb][half * 2], bl[nb][half * 2 + 1]);
                    mma16816(cc, al[mi], bh[nb][half * 2], bh[nb][half * 2 + 1]);
                }
    }
}

// fp32 epilogue (direct from regs)
__device__ __forceinline__ void epilogue_f32(
    float c[2][4][4], float* __restrict__ C, const float* __restrict__ bias,
    int ldc, int m0, int cn0, int mrow0, int ncol0, int lane)
{
#pragma unroll
    for (int mi = 0; mi < 2; ++mi) {
        int r = m0 + mrow0 + mi * 16 + (lane >> 2);
#pragma unroll
        for (int ni = 0; ni < 4; ++ni) {
            int cl = ncol0 + ni * 8 + ((lane & 3) << 1);
            float b0 = 0.f, b1 = 0.f;
            if (bias) { b0 = bias[cl]; b1 = bias[cl + 1]; }
            float2 v0 = make_float2(c[mi][ni][0] + b0, c[mi][ni][1] + b1);
            float2 v1 = make_float2(c[mi][ni][2] + b0, c[mi][ni][3] + b1);
            *(float2*)(C + (size_t)r * ldc + cn0 + cl) = v0;
            *(float2*)(C + (size_t)(r + 8) * ldc + cn0 + cl) = v1;
        }
    }
}

// bf16 hi/lo split epilogue into g_qkh/g_qkl ([row][512], col base zbase)
__device__ __forceinline__ void epilogue_split(
    float c[2][4][4], const float* __restrict__ bias,
    int m0, int zbase, int mrow0, int ncol0, int lane)
{
#pragma unroll
    for (int mi = 0; mi < 2; ++mi) {
        int r = m0 + mrow0 + mi * 16 + (lane >> 2);
#pragma unroll
        for (int ni = 0; ni < 4; ++ni) {
            int cl = ncol0 + ni * 8 + ((lane & 3) << 1);
            float b0 = bias[cl], b1 = bias[cl + 1];
            uint32_t h0, l0, h1, l1;
            splitpk(c[mi][ni][0] + b0, c[mi][ni][1] + b1, h0, l0);
            splitpk(c[mi][ni][2] + b0, c[mi][ni][3] + b1, h1, l1);
            size_t o0 = (size_t)r * 512 + zbase + cl;
            size_t o1 = (size_t)(r + 8) * 512 + zbase + cl;
            *(uint32_t*)(g_qkh + o0) = h0;
            *(uint32_t*)(g_qkl + o0) = l0;
            *(uint32_t*)(g_qkh + o1) = h1;
            *(uint32_t*)(g_qkl + o1) = l1;
        }
    }
}

// ---------------------------------------------------------------------------
// TN GEMM body: 512 threads, 16 warps (4x4), double-buffered.
// ---------------------------------------------------------------------------
__device__ __forceinline__ void gemm_tn_body(
    char* sm, float c[2][4][4],
    const float* __restrict__ A, const float* __restrict__ B,
    int K, int lda, int ldb, int m0,
    int lane, int mrow0, int ncol0)
{
    const int tid = threadIdx.x;
    const int row = tid >> 2, kh = (tid & 3) * 8;

    const float* pA = A + (size_t)(m0 + row) * lda + kh;
    const float* pB = B + (size_t)row * ldb + kh;

    float4 fa[2], fb[2];
    fa[0] = *(const float4*)(pA);     fa[1] = *(const float4*)(pA + 4);
    fb[0] = *(const float4*)(pB);     fb[1] = *(const float4*)(pB + 4);
    {
        uint16_t* b0 = (uint16_t*)sm;
        stage_tn512(b0,             b0 + TN_TILE_B / 2,     fa, tid);
        stage_tn512(b0 + TN_TILE_B, b0 + 3 * TN_TILE_B / 2, fb, tid);
    }
    __syncthreads();

    int ib = 0;
    for (int k0 = 0; k0 < K; k0 += 32, ib ^= 1) {
        const bool has_next = (k0 + 32 < K);
        if (has_next) {
            fa[0] = *(const float4*)(pA + k0 + 32);
            fa[1] = *(const float4*)(pA + k0 + 36);
            fb[0] = *(const float4*)(pB + k0 + 32);
            fb[1] = *(const float4*)(pB + k0 + 36);
        }
        uint16_t* cur = (uint16_t*)(sm + ib * TN_BUF_B);
        compute_chunk<false>(c, cur, cur + TN_TILE_B / 2,
                             cur + TN_TILE_B, cur + 3 * TN_TILE_B / 2,
                             lane, mrow0, ncol0);
        if (has_next) {
            uint16_t* nxt = (uint16_t*)(sm + (ib ^ 1) * TN_BUF_B);
            stage_tn512(nxt,             nxt + TN_TILE_B / 2,     fa, tid);
            stage_tn512(nxt + TN_TILE_B, nxt + 3 * TN_TILE_B / 2, fb, tid);
        }
        __syncthreads();
    }
}

__global__ __launch_bounds__(512, 1) void mma_qkv(
    const float* __restrict__ x,
    const float* __restrict__ Wq, const float* __restrict__ bq,
    const float* __restrict__ Wk, const float* __restrict__ bk,
    const float* __restrict__ Wv, const float* __restrict__ bv)
{
    extern __shared__ __align__(16) char sm[];
    const int tid = threadIdx.x, lane = tid & 31, warp = tid >> 5;
    const int mrow0 = (warp & 3) * 32, ncol0 = (warp >> 2) * 32;
    const int z = blockIdx.x;
    const int m0 = blockIdx.y * 128;
    const float* B; const float* bias;
    if (z < 2)      { B = Wq + (size_t)z * 128 * 256;       bias = bq + z * 128; }
    else if (z < 4) { B = Wk + (size_t)(z - 2) * 128 * 256; bias = bk + (z - 2) * 128; }
    else            { B = Wv + (size_t)(z - 4) * 128 * 256; bias = bv + (z - 4) * 128; }

    float c[2][4][4];
#pragma unroll
    for (int i = 0; i < 2; ++i)
#pragma unroll
        for (int j = 0; j < 4; ++j)
#pragma unroll
            for (int q = 0; q < 4; ++q) c[i][j][q] = 0.f;

    gemm_tn_body(sm, c, x, B, 256, 256, 256, m0, lane, mrow0, ncol0);

    if (z < 4) epilogue_split(c, bias, m0, z * 128, mrow0, ncol0, lane);
    else       epilogue_f32(c, g_v, bias, 256, m0, (z - 4) * 128, mrow0, ncol0, lane);
}

__global__ __launch_bounds__(512, 1) void mma_out(
    const float* __restrict__ Wo, const float* __restrict__ bo,
    float* __restrict__ out)
{
    extern __shared__ __align__(16) char sm[];
    const int tid = threadIdx.x, lane = tid & 31, warp = tid >> 5;
    const int mrow0 = (warp & 3) * 32, ncol0 = (warp >> 2) * 32;
    const int n0 = blockIdx.x * 128;
    const int m0 = blockIdx.y * 128;

    float c[2][4][4];
#pragma unroll
    for (int i = 0; i < 2; ++i)
#pragma unroll
        for (int j = 0; j < 4; ++j)
#pragma unroll
            for (int q = 0; q < 4; ++q) c[i][j][q] = 0.f;

    gemm_tn_body(sm, c, g_tmp, Wo + (size_t)n0 * 256, 256, 256, 256, m0,
                 lane, mrow0, ncol0);
    epilogue_f32(c, out, bo + n0, 256, m0, n0, mrow0, ncol0, lane);
}

// ---------------------------------------------------------------------------
// NN batched: tmp[b] = avg[b](512x512) @ v[b](512x256)   512 threads
// ---------------------------------------------------------------------------
__global__ __launch_bounds__(512, 1) void mma_nn(
    const float* __restrict__ avg, float* __restrict__ tmp)
{
    extern __shared__ __align__(16) char sm[];
    const int tid = threadIdx.x, lane = tid & 31, warp = tid >> 5;
    const int mrow0 = (warp & 3) * 32, ncol0 = (warp >> 2) * 32;
    const int n0 = blockIdx.x * 128;
    const int m0 = blockIdx.y * 128;
    const int b  = blockIdx.z;

    const float* A = avg + (size_t)b * 512 * 512;
    const float* B = g_v + (size_t)b * 512 * 256;

    float c[2][4][4];
#pragma unroll
    for (int i = 0; i < 2; ++i)
#pragma unroll
        for (int j = 0; j < 4; ++j)
#pragma unroll
            for (int q = 0; q < 4; ++q) c[i][j][q] = 0.f;

    const int row = tid >> 2, kh = (tid & 3) * 8;      // A loader
    const int bk = tid >> 4, bn = (tid & 15) * 8;      // B loader
    const float* pA = A + (size_t)(m0 + row) * 512 + kh;
    const float* pB = B + n0 + bn;

    float4 fa[2], fb[2];
    fa[0] = *(const float4*)(pA);
    fa[1] = *(const float4*)(pA + 4);
    fb[0] = *(const float4*)(pB + (size_t)bk * 256);
    fb[1] = *(const float4*)(pB + (size_t)bk * 256 + 4);
    {
        uint16_t* a0 = (uint16_t*)sm;
        uint16_t* b0 = (uint16_t*)(sm + 2 * TN_TILE_B);
        stage_tn512(a0, a0 + TN_TILE_B / 2, fa, tid);
        stage_nn_b512(b0, b0 + NN_BT_B / 2, fb, tid);
    }
    __syncthreads();

    int ib = 0;
    for (int k0 = 0; k0 < 512; k0 += 32, ib ^= 1) {
        const bool has_next = (k0 + 32 < 512);
        if (has_next) {
            fa[0] = *(const float4*)(pA + k0 + 32);
            fa[1] = *(const float4*)(pA + k0 + 36);
            fb[0] = *(const float4*)(pB + (size_t)(k0 + 32 + bk) * 256);
            fb[1] = *(const float4*)(pB + (size_t)(k0 + 32 + bk) * 256 + 4);
        }
        uint16_t* ca = (uint16_t*)(sm + ib * NN_BUF_B);
        uint16_t* cb = (uint16_t*)(sm + ib * NN_BUF_B + 2 * TN_TILE_B);
        compute_chunk<true>(c, ca, ca + TN_TILE_B / 2, cb, cb + NN_BT_B / 2,
                            lane, mrow0, ncol0);
        if (has_next) {
            uint16_t* na = (uint16_t*)(sm + (ib ^ 1) * NN_BUF_B);
            uint16_t* nb = (uint16_t*)(sm + (ib ^ 1) * NN_BUF_B + 2 * TN_TILE_B);
            stage_tn512(na, na + TN_TILE_B / 2, fa, tid);
            stage_nn_b512(nb, nb + NN_BT_B / 2, fb, tid);
        }
        __syncthreads();
    }
    epilogue_f32(c, tmp, nullptr, 256, b * 512 + m0, n0, mrow0, ncol0, lane);
}

// ---------------------------------------------------------------------------
// Attention: tensor-pipe scores from PRE-SPLIT bf16 q/k (pure-copy staging),
// interleaved dual-query exact sparsemax.
// ---------------------------------------------------------------------------
#define SC_STR 522
#define AK_OFF   0
#define AKL_OFF  20480
#define AQ_OFF   40960
#define AQL_OFF  43520
#define ASC_OFF  46080
#define ATTN_SMEM_BYTES (46080 + 32 * SC_STR * 4)   // 112896

__global__ __launch_bounds__(512, 2) void attn_sparsemax_kernel(float* __restrict__ avg)
{
    extern __shared__ __align__(16) char sm[];
    uint16_t* Khi = (uint16_t*)(sm + AK_OFF);
    uint16_t* Klo = (uint16_t*)(sm + AKL_OFF);
    uint16_t* Qhi = (uint16_t*)(sm + AQ_OFF);
    uint16_t* Qlo = (uint16_t*)(sm + AQL_OFF);
    float*    Ssc = (float*)(sm + ASC_OFF);

    const int tid  = threadIdx.x;
    const int lane = tid & 31, w = tid >> 5;
    const int b    = blockIdx.x >> 4;
    const int s0   = (blockIdx.x & 15) << 5;

    const uint16_t* qkh = g_qkh + (size_t)b * 512 * 512;
    const uint16_t* qkl = g_qkl + (size_t)b * 512 * 512;

    float acc[2][16];
#pragma unroll
    for (int qi = 0; qi < 2; ++qi)
#pragma unroll
        for (int i = 0; i < 16; ++i) acc[qi][i] = 0.f;

    const int lr = lane & 7, lg = lane >> 3;

    for (int h = 0; h < HH; ++h) {
        __syncthreads();

        // ---- stage Q (32 x 32) hi/lo: pure copy ----
        if (tid < 256) {
            int r = (tid & 127) >> 2, e8 = (tid & 3) * 8;
            const uint16_t* src = (tid < 128 ? qkh : qkl);
            uint16_t* dst = (tid < 128 ? Qhi : Qlo);
            *(uint4*)(dst + r * AT_STR + e8) =
                *(const uint4*)(src + (size_t)(s0 + r) * 512 + h * 32 + e8);
        }

#pragma unroll
        for (int ck = 0; ck < 2; ++ck) {
            if (ck) __syncthreads();
            // ---- stage K chunk (256 x 32) hi/lo: pure copy ----
            {
                int r = tid >> 1, e16 = (tid & 1) * 16;
                size_t gofs = (size_t)(ck * 256 + r) * 512 + 256 + h * 32 + e16;
                *(uint4*)(Khi + r * AT_STR + e16)     = *(const uint4*)(qkh + gofs);
                *(uint4*)(Khi + r * AT_STR + e16 + 8) = *(const uint4*)(qkh + gofs + 8);
                *(uint4*)(Klo + r * AT_STR + e16)     = *(const uint4*)(qkl + gofs);
                *(uint4*)(Klo + r * AT_STR + e16 + 8) = *(const uint4*)(qkl + gofs + 8);
            }
            __syncthreads();

            float c[2][2][4];
#pragma unroll
            for (int mi = 0; mi < 2; ++mi)
#pragma unroll
                for (int hf = 0; hf < 2; ++hf)
#pragma unroll
                    for (int q = 0; q < 4; ++q) c[mi][hf][q] = 0.f;

#pragma unroll
            for (int k16 = 0; k16 < 32; k16 += 16) {
                uint32_t aoff = (uint32_t)(((lane & 15) * AT_STR + k16 + ((lane >> 4) << 3)) * 2);
                uint32_t ah[2][4], al[2][4];
#pragma unroll
                for (int mi = 0; mi < 2; ++mi) {
                    ldmx4(ah[mi], cvta_s(Qhi) + aoff + mi * (16 * AT_STR * 2));
                    ldmx4(al[mi], cvta_s(Qlo) + aoff + mi * (16 * AT_STR * 2));
                }
                uint32_t boff = (uint32_t)(((w * 16 + lr + ((lg & 2) << 2)) * AT_STR
                                            + k16 + ((lg & 1) << 3)) * 2);
                uint32_t bh[4], bl[4];
                ldmx4(bh, cvta_s(Khi) + boff);
                ldmx4(bl, cvta_s(Klo) + boff);
#pragma unroll
                for (int mi = 0; mi < 2; ++mi)
#pragma unroll
                    for (int hf = 0; hf < 2; ++hf) {
                        float* cc = c[mi][hf];
                        mma16816(cc, ah[mi], bh[hf * 2], bh[hf * 2 + 1]);
                        mma16816(cc, ah[mi], bl[hf * 2], bl[hf * 2 + 1]);
                        mma16816(cc, al[mi], bh[hf * 2], bh[hf * 2 + 1]);
                    }
            }

#pragma unroll
            for (int mi = 0; mi < 2; ++mi)
#pragma unroll
                for (int hf = 0; hf < 2; ++hf) {
                    int gc = ck * 256 + w * 16 + hf * 8 + ((lane & 3) << 1);
                    int r0 = mi * 16 + (lane >> 2);
                    int r1 = r0 + 8;
                    float v0 = c[mi][hf][0] * 0.17677669529663687f;
                    float v1 = c[mi][hf][1] * 0.17677669529663687f;
                    float v2 = c[mi][hf][2] * 0.17677669529663687f;
                    float v3 = c[mi][hf][3] * 0.17677669529663687f;
                    if (gc     == s0 + r0) v0 = -CUDART_INF_F;
                    if (gc + 1 == s0 + r0) v1 = -CUDART_INF_F;
                    if (gc     == s0 + r1) v2 = -CUDART_INF_F;
                    if (gc + 1 == s0 + r1) v3 = -CUDART_INF_F;
                    *(float2*)&Ssc[r0 * SC_STR + gc] = make_float2(v0, v1);
                    *(float2*)&Ssc[r1 * SC_STR + gc] = make_float2(v2, v3);
                }
        }
        __syncthreads();

        // ---- dual-query exact sparsemax (Michelot), interleaved ----
        float zz0[16], zz1[16];
        {
            int q0 = w * 2, q1 = w * 2 + 1;
#pragma unroll
            for (int i = 0; i < 16; ++i) {
                zz0[i] = Ssc[q0 * SC_STR + lane + 32 * i];
                zz1[i] = Ssc[q1 * SC_STR + lane + 32 * i];
            }
        }
        float tau0 = -CUDART_INF_F, tau1 = -CUDART_INF_F;
        int prev0 = -1, prev1 = -1;
        bool done0 = false, done1 = false;
        for (int it = 0; it < 64; ++it) {
            float sa0 = 0.f, sa1 = 0.f;
            int ca0 = 0, ca1 = 0;
#pragma unroll
            for (int i = 0; i < 16; ++i) {
                if (zz0[i] > tau0) { sa0 += zz0[i]; ca0++; }
                if (zz1[i] > tau1) { sa1 += zz1[i]; ca1++; }
            }
#pragma unroll
            for (int o = 16; o; o >>= 1) {
                sa0 += __shfl_xor_sync(0xffffffffu, sa0, o);
                sa1 += __shfl_xor_sync(0xffffffffu, sa1, o);
            }
            ca0 = __reduce_add_sync(0xffffffffu, ca0);
            ca1 = __reduce_add_sync(0xffffffffu, ca1);
            if (!done0) {
                if (ca0 == prev0 || ca0 == 0) done0 = true;
                else { prev0 = ca0; tau0 = (sa0 - 1.0f) / (float)ca0; }
            }
            if (!done1) {
                if (ca1 == prev1 || ca1 == 0) done1 = true;
                else { prev1 = ca1; tau1 = (sa1 - 1.0f) / (float)ca1; }
            }
            if (done0 && done1) break;
        }
#pragma unroll
        for (int i = 0; i < 16; ++i) {
            acc[0][i] += fmaxf(zz0[i] - tau0, 0.f) * 0.125f;
            acc[1][i] += fmaxf(zz1[i] - tau1, 0.f) * 0.125f;
        }
    }

#pragma unroll
    for (int qi = 0; qi < 2; ++qi) {
        float* dst = avg + (size_t)(b * 512 + s0 + w * 2 + qi) * 512;
#pragma unroll
        for (int i = 0; i < 16; ++i) dst[lane + 32 * i] = acc[qi][i];
    }
}

// ---------------------------------------------------------------------------
extern "C" void kernel_launch(void* const* d_in, const int* in_sizes, int n_in,
                              void* d_out, int out_size)
{
    const float* x  = (const float*)d_in[0];
    const float* Wq = (const float*)d_in[1];
    const float* bq = (const float*)d_in[2];
    const float* Wk = (const float*)d_in[3];
    const float* bk = (const float*)d_in[4];
    const float* Wv = (const float*)d_in[5];
    const float* bv = (const float*)d_in[6];
    const float* Wo = (const float*)d_in[7];
    const float* bo = (const float*)d_in[8];

    float* out = (float*)d_out;                        // [32,512,256]
    float* avg = out + (size_t)NROWS * DD;             // [32,512,512]

    float* tmp = nullptr;
    cudaGetSymbolAddress((void**)&tmp, g_tmp);

    cudaFuncSetAttribute(mma_qkv, cudaFuncAttributeMaxDynamicSharedMemorySize, TN_SMEM_B);
    cudaFuncSetAttribute(mma_out, cudaFuncAttributeMaxDynamicSharedMemorySize, TN_SMEM_B);
    cudaFuncSetAttribute(mma_nn,  cudaFuncAttributeMaxDynamicSharedMemorySize, NN_SMEM_B);
    cudaFuncSetAttribute(attn_sparsemax_kernel,
                         cudaFuncAttributeMaxDynamicSharedMemorySize, ATTN_SMEM_BYTES);

    // 1) QKV projections: q,k -> bf16 hi/lo (pre-split); v -> fp32
    {
        dim3 grid(6, 128);
        mma_qkv<<<grid, 512, TN_SMEM_B>>>(x, Wq, bq, Wk, bk, Wv, bv);
    }

    // 2) scores (HMMA) + sparsemax + head average -> avg_attention (in d_out)
    attn_sparsemax_kernel<<<NROWS / 32, 512, ATTN_SMEM_BYTES>>>(avg);

    // 3) tmp[b] = avg[b] @ v[b]
    {
        dim3 grid(2, 4, BB);
        mma_nn<<<grid, 512, NN_SMEM_B>>>(avg, tmp);
    }

    // 4) out = tmp @ Wo^T + bo
    {
        dim3 grid(2, 128);
        mma_out<<<grid, 512, TN_SMEM_B>>>(Wo, bo, out);
    }
}

// round 13
// speedup vs baseline: 1.4551x; 1.4551x over previous
#include <cuda_runtime.h>
#include <cuda_bf16.h>
#include <cstdint>
#include <math.h>
#include <math_constants.h>

// Problem constants
#define BB 32
#define SS 512
#define DD 256
#define HH 8
#define DHH 32
#define NROWS (BB*SS)

// Scratch (__device__ globals; allocation is banned)
__device__ uint16_t g_qkh[(size_t)NROWS * 512];   // bf16 hi: [row][0:256)=q, [256:512)=k
__device__ uint16_t g_qkl[(size_t)NROWS * 512];   // bf16 lo
__device__ float    g_v[(size_t)NROWS * 256];     // v fp32  [b*512+t][e]
__device__ float    g_tmp[(size_t)NROWS * 256];   // avg @ v result

// ---------------------------------------------------------------------------
// bf16 split + pack helpers (3xBF16 fp32 emulation)
// ---------------------------------------------------------------------------
__device__ __forceinline__ void splitpk(float x, float y, uint32_t& h, uint32_t& l) {
    __nv_bfloat16 hx = __float2bfloat16(x), hy = __float2bfloat16(y);
    float rx = x - __bfloat162float(hx);
    float ry = y - __bfloat162float(hy);
    __nv_bfloat16 lx = __float2bfloat16(rx), ly = __float2bfloat16(ry);
    h = (uint32_t)__bfloat16_as_ushort(hx) | ((uint32_t)__bfloat16_as_ushort(hy) << 16);
    l = (uint32_t)__bfloat16_as_ushort(lx) | ((uint32_t)__bfloat16_as_ushort(ly) << 16);
}

__device__ __forceinline__ uint32_t cvta_s(const void* p) {
    return (uint32_t)__cvta_generic_to_shared(p);
}

__device__ __forceinline__ void ldmx4(uint32_t r[4], uint32_t addr) {
    asm volatile("ldmatrix.sync.aligned.m8n8.x4.shared.b16 {%0,%1,%2,%3}, [%4];"
                 : "=r"(r[0]), "=r"(r[1]), "=r"(r[2]), "=r"(r[3]) : "r"(addr));
}
__device__ __forceinline__ void ldmx4t(uint32_t r[4], uint32_t addr) {
    asm volatile("ldmatrix.sync.aligned.m8n8.x4.trans.shared.b16 {%0,%1,%2,%3}, [%4];"
                 : "=r"(r[0]), "=r"(r[1]), "=r"(r[2]), "=r"(r[3]) : "r"(addr));
}

__device__ __forceinline__ void mma16816(float c[4], const uint32_t a[4],
                                         uint32_t b0, uint32_t b1) {
    asm volatile(
        "mma.sync.aligned.m16n8k16.row.col.f32.bf16.bf16.f32 "
        "{%0,%1,%2,%3}, {%4,%5,%6,%7}, {%8,%9}, {%0,%1,%2,%3};"
        : "+f"(c[0]), "+f"(c[1]), "+f"(c[2]), "+f"(c[3])
        : "r"(a[0]), "r"(a[1]), "r"(a[2]), "r"(a[3]), "r"(b0), "r"(b1));
}

// ---------------------------------------------------------------------------
// Tile strides
// ---------------------------------------------------------------------------
#define AT_STR 40    // K-major tiles: 32 k + 8 pad
#define BN_STR 136   // NN B tile [k][n]: 128 n + 8 pad

#define TN_TILE_B  (128 * AT_STR * 2)            // 10240
#define TN_BUF_B   (4 * TN_TILE_B)               // 40960
#define TN_SMEM_B  (2 * TN_BUF_B)                // 81920

#define NN_BT_B    (32 * BN_STR * 2)             // 8704
#define NN_BUF_B   (2 * TN_TILE_B + 2 * NN_BT_B) // 37888
#define NN_SMEM_B  (2 * NN_BUF_B)                // 75776

// Stage a 128x32 fp32 K-contig tile -> hi/lo bf16 smem (row stride AT_STR)
__device__ __forceinline__ void stage_tn(uint16_t* hi, uint16_t* lo,
                                         const float4 f[4], int tid) {
    int row = tid >> 1, kh = (tid & 1) * 16;
    uint4 H0, H1, L0, L1;
    splitpk(f[0].x, f[0].y, H0.x, L0.x); splitpk(f[0].z, f[0].w, H0.y, L0.y);
    splitpk(f[1].x, f[1].y, H0.z, L0.z); splitpk(f[1].z, f[1].w, H0.w, L0.w);
    splitpk(f[2].x, f[2].y, H1.x, L1.x); splitpk(f[2].z, f[2].w, H1.y, L1.y);
    splitpk(f[3].x, f[3].y, H1.z, L1.z); splitpk(f[3].z, f[3].w, H1.w, L1.w);
    *(uint4*)(hi + row * AT_STR + kh)     = H0;
    *(uint4*)(hi + row * AT_STR + kh + 8) = H1;
    *(uint4*)(lo + row * AT_STR + kh)     = L0;
    *(uint4*)(lo + row * AT_STR + kh + 8) = L1;
}

// Stage a 32x128 fp32 N-contig tile -> hi/lo bf16 smem [k][n] (stride BN_STR)
__device__ __forceinline__ void stage_nn_b(uint16_t* hi, uint16_t* lo,
                                           const float4 f[4], int tid) {
    int k = tid >> 3, nq = (tid & 7) * 16;
    uint4 H0, H1, L0, L1;
    splitpk(f[0].x, f[0].y, H0.x, L0.x); splitpk(f[0].z, f[0].w, H0.y, L0.y);
    splitpk(f[1].x, f[1].y, H0.z, L0.z); splitpk(f[1].z, f[1].w, H0.w, L0.w);
    splitpk(f[2].x, f[2].y, H1.x, L1.x); splitpk(f[2].z, f[2].w, H1.y, L1.y);
    splitpk(f[3].x, f[3].y, H1.z, L1.z); splitpk(f[3].z, f[3].w, H1.w, L1.w);
    *(uint4*)(hi + k * BN_STR + nq)     = H0;
    *(uint4*)(hi + k * BN_STR + nq + 8) = H1;
    *(uint4*)(lo + k * BN_STR + nq)     = L0;
    *(uint4*)(lo + k * BN_STR + nq + 8) = L1;
}

// Warp-level K-chunk compute: 64x32 warp tile, 3-pass split.
template<bool TRANSB>
__device__ __forceinline__ void compute_chunk(
    float c[4][4][4],
    const uint16_t* sAhi, const uint16_t* sAlo,
    const uint16_t* sBhi, const uint16_t* sBlo,
    int lane, int mrow0, int ncol0)
{
    const int lr = lane & 7, lg = lane >> 3;
#pragma unroll
    for (int k16 = 0; k16 < 32; k16 += 16) {
        uint32_t ah[4][4], al[4][4];
        uint32_t aoff = (uint32_t)(((mrow0 + (lane & 15)) * AT_STR + k16 + ((lane >> 4) << 3)) * 2);
#pragma unroll
        for (int mi = 0; mi < 4; ++mi) {
            ldmx4(ah[mi], cvta_s(sAhi) + aoff + mi * (16 * AT_STR * 2));
            ldmx4(al[mi], cvta_s(sAlo) + aoff + mi * (16 * AT_STR * 2));
        }
        uint32_t bh[2][4], bl[2][4];
#pragma unroll
        for (int nb = 0; nb < 2; ++nb) {
            uint32_t boff;
            if (TRANSB) {
                boff = (uint32_t)(((k16 + lr + ((lg & 1) << 3)) * BN_STR
                                   + ncol0 + nb * 16 + ((lg & 2) << 2)) * 2);
                ldmx4t(bh[nb], cvta_s(sBhi) + boff);
                ldmx4t(bl[nb], cvta_s(sBlo) + boff);
            } else {
                boff = (uint32_t)(((ncol0 + nb * 16 + lr + ((lg & 2) << 2)) * AT_STR
                                   + k16 + ((lg & 1) << 3)) * 2);
                ldmx4(bh[nb], cvta_s(sBhi) + boff);
                ldmx4(bl[nb], cvta_s(sBlo) + boff);
            }
        }
#pragma unroll
        for (int mi = 0; mi < 4; ++mi)
#pragma unroll
            for (int nb = 0; nb < 2; ++nb)
#pragma unroll
                for (int half = 0; half < 2; ++half) {
                    float* cc = c[mi][nb * 2 + half];
                    mma16816(cc, ah[mi], bh[nb][half * 2], bh[nb][half * 2 + 1]);
                    mma16816(cc, ah[mi], bl[nb][half * 2], bl[nb][half * 2 + 1]);
                    mma16816(cc, al[mi], bh[nb][half * 2], bh[nb][half * 2 + 1]);
                }
    }
}

__device__ __forceinline__ void epilogue_store(
    float c[4][4][4], float* __restrict__ C, const float* __restrict__ bias,
    int ldc, int m0, int cn0, int mrow0, int ncol0, int lane)
{
#pragma unroll
    for (int mi = 0; mi < 4; ++mi) {
        int r = m0 + mrow0 + mi * 16 + (lane >> 2);
#pragma unroll
        for (int ni = 0; ni < 4; ++ni) {
            int cl = ncol0 + ni * 8 + ((lane & 3) << 1);
            float b0 = 0.f, b1 = 0.f;
            if (bias) { b0 = bias[cl]; b1 = bias[cl + 1]; }
            float2 v0 = make_float2(c[mi][ni][0] + b0, c[mi][ni][1] + b1);
            float2 v1 = make_float2(c[mi][ni][2] + b0, c[mi][ni][3] + b1);
            *(float2*)(C + (size_t)r * ldc + cn0 + cl) = v0;
            *(float2*)(C + (size_t)(r + 8) * ldc + cn0 + cl) = v1;
        }
    }
}

// Split epilogue: write q/k as bf16 hi/lo into g_qkh/g_qkl (row len 512)
__device__ __forceinline__ void epilogue_split(
    float c[4][4][4], const float* __restrict__ bias,
    int m0, int zbase, int mrow0, int ncol0, int lane)
{
#pragma unroll
    for (int mi = 0; mi < 4; ++mi) {
        int r = m0 + mrow0 + mi * 16 + (lane >> 2);
#pragma unroll
        for (int ni = 0; ni < 4; ++ni) {
            int cl = ncol0 + ni * 8 + ((lane & 3) << 1);
            float b0 = bias[cl], b1 = bias[cl + 1];
            uint32_t h0, l0, h1, l1;
            splitpk(c[mi][ni][0] + b0, c[mi][ni][1] + b1, h0, l0);
            splitpk(c[mi][ni][2] + b0, c[mi][ni][3] + b1, h1, l1);
            size_t o0 = (size_t)r * 512 + zbase + cl;
            size_t o1 = (size_t)(r + 8) * 512 + zbase + cl;
            *(uint32_t*)(g_qkh + o0) = h0;
            *(uint32_t*)(g_qkl + o0) = l0;
            *(uint32_t*)(g_qkh + o1) = h1;
            *(uint32_t*)(g_qkl + o1) = l1;
        }
    }
}

// ---------------------------------------------------------------------------
// TN GEMM body — 256 threads, 8 warps (2x4), double-buffered.
// ---------------------------------------------------------------------------
__device__ __forceinline__ void gemm_tn_mma_body(
    char* sm, float c[4][4][4],
    const float* __restrict__ A, const float* __restrict__ B,
    int K, int lda, int ldb, int m0, int lane, int mrow0, int ncol0)
{
    const int tid = threadIdx.x;
    const int row = tid >> 1, kh = (tid & 1) * 16;

    const float* pA = A + (size_t)(m0 + row) * lda + kh;
    const float* pB = B + (size_t)row * ldb + kh;

    float4 fa[4], fb[4];
#pragma unroll
    for (int i = 0; i < 4; ++i) {
        fa[i] = *(const float4*)(pA + i * 4);
        fb[i] = *(const float4*)(pB + i * 4);
    }
    {
        uint16_t* b0 = (uint16_t*)sm;
        stage_tn(b0,             b0 + TN_TILE_B / 2,     fa, tid);
        stage_tn(b0 + TN_TILE_B, b0 + 3 * TN_TILE_B / 2, fb, tid);
    }
    __syncthreads();

    int ib = 0;
    for (int k0 = 0; k0 < K; k0 += 32, ib ^= 1) {
        const bool has_next = (k0 + 32 < K);
        if (has_next) {
#pragma unroll
            for (int i = 0; i < 4; ++i) {
                fa[i] = *(const float4*)(pA + k0 + 32 + i * 4);
                fb[i] = *(const float4*)(pB + k0 + 32 + i * 4);
            }
        }
        uint16_t* cur = (uint16_t*)(sm + ib * TN_BUF_B);
        compute_chunk<false>(c, cur, cur + TN_TILE_B / 2,
                             cur + TN_TILE_B, cur + 3 * TN_TILE_B / 2,
                             lane, mrow0, ncol0);
        if (has_next) {
            uint16_t* nxt = (uint16_t*)(sm + (ib ^ 1) * TN_BUF_B);
            stage_tn(nxt,             nxt + TN_TILE_B / 2,     fa, tid);
            stage_tn(nxt + TN_TILE_B, nxt + 3 * TN_TILE_B / 2, fb, tid);
        }
        __syncthreads();
    }
}

__global__ __launch_bounds__(256) void mma_qkv(
    const float* __restrict__ x,
    const float* __restrict__ Wq, const float* __restrict__ bq,
    const float* __restrict__ Wk, const float* __restrict__ bk,
    const float* __restrict__ Wv, const float* __restrict__ bv)
{
    extern __shared__ __align__(16) char sm[];
    const int tid = threadIdx.x, lane = tid & 31, warp = tid >> 5;
    const int mrow0 = (warp & 1) * 64, ncol0 = (warp >> 1) * 32;
    const int z = blockIdx.x;
    const int m0 = blockIdx.y * 128;
    const float* B; const float* bias;
    if (z < 2)      { B = Wq + (size_t)z * 128 * 256;       bias = bq + z * 128; }
    else if (z < 4) { B = Wk + (size_t)(z - 2) * 128 * 256; bias = bk + (z - 2) * 128; }
    else            { B = Wv + (size_t)(z - 4) * 128 * 256; bias = bv + (z - 4) * 128; }

    float c[4][4][4];
#pragma unroll
    for (int i = 0; i < 4; ++i)
#pragma unroll
        for (int j = 0; j < 4; ++j)
#pragma unroll
            for (int q = 0; q < 4; ++q) c[i][j][q] = 0.f;

    gemm_tn_mma_body(sm, c, x, B, 256, 256, 256, m0, lane, mrow0, ncol0);

    if (z < 4) epilogue_split(c, bias, m0, z * 128, mrow0, ncol0, lane);
    else       epilogue_store(c, g_v, bias, 256, m0, (z - 4) * 128, mrow0, ncol0, lane);
}

__global__ __launch_bounds__(256) void mma_out(
    const float* __restrict__ Wo, const float* __restrict__ bo,
    float* __restrict__ out)
{
    extern __shared__ __align__(16) char sm[];
    const int tid = threadIdx.x, lane = tid & 31, warp = tid >> 5;
    const int mrow0 = (warp & 1) * 64, ncol0 = (warp >> 1) * 32;
    const int n0 = blockIdx.x * 128;
    const int m0 = blockIdx.y * 128;

    float c[4][4][4];
#pragma unroll
    for (int i = 0; i < 4; ++i)
#pragma unroll
        for (int j = 0; j < 4; ++j)
#pragma unroll
            for (int q = 0; q < 4; ++q) c[i][j][q] = 0.f;

    gemm_tn_mma_body(sm, c, g_tmp, Wo + (size_t)n0 * 256, 256, 256, 256, m0,
                     lane, mrow0, ncol0);
    epilogue_store(c, out, bo + n0, 256, m0, n0, mrow0, ncol0, lane);
}

// ---------------------------------------------------------------------------
// NN batched (double-buffered): tmp[b] = avg[b] @ v[b]   (v from g_v, ldb=256)
// ---------------------------------------------------------------------------
__global__ __launch_bounds__(256) void mma_nn(
    const float* __restrict__ avg, float* __restrict__ tmp)
{
    extern __shared__ __align__(16) char sm[];
    const int tid = threadIdx.x;
    const int lane = tid & 31, warp = tid >> 5;
    const int mrow0 = (warp & 1) * 64, ncol0 = (warp >> 1) * 32;
    const int n0 = blockIdx.x * 128;
    const int m0 = blockIdx.y * 128;
    const int b  = blockIdx.z;

    const float* A = avg + (size_t)b * 512 * 512;
    const float* B = g_v + (size_t)b * 512 * 256;

    float c[4][4][4];
#pragma unroll
    for (int i = 0; i < 4; ++i)
#pragma unroll
        for (int j = 0; j < 4; ++j)
#pragma unroll
            for (int q = 0; q < 4; ++q) c[i][j][q] = 0.f;

    const int row = tid >> 1, kh = (tid & 1) * 16;
    const int bk = tid >> 3, bn = (tid & 7) * 16;
    const float* pA = A + (size_t)(m0 + row) * 512 + kh;
    const float* pB = B + n0 + bn;

    float4 fa[4], fb[4];
#pragma unroll
    for (int i = 0; i < 4; ++i) {
        fa[i] = *(const float4*)(pA + i * 4);
        fb[i] = *(const float4*)(pB + (size_t)bk * 256 + i * 4);
    }
    {
        uint16_t* a0 = (uint16_t*)sm;
        uint16_t* b0 = (uint16_t*)(sm + 2 * TN_TILE_B);
        stage_tn(a0, a0 + TN_TILE_B / 2, fa, tid);
        stage_nn_b(b0, b0 + NN_BT_B / 2, fb, tid);
    }
    __syncthreads();

    int ib = 0;
    for (int k0 = 0; k0 < 512; k0 += 32, ib ^= 1) {
        const bool has_next = (k0 + 32 < 512);
        if (has_next) {
#pragma unroll
            for (int i = 0; i < 4; ++i) {
                fa[i] = *(const float4*)(pA + k0 + 32 + i * 4);
                fb[i] = *(const float4*)(pB + (size_t)(k0 + 32 + bk) * 256 + i * 4);
            }
        }
        uint16_t* ca = (uint16_t*)(sm + ib * NN_BUF_B);
        uint16_t* cb = (uint16_t*)(sm + ib * NN_BUF_B + 2 * TN_TILE_B);
        compute_chunk<true>(c, ca, ca + TN_TILE_B / 2, cb, cb + NN_BT_B / 2,
                            lane, mrow0, ncol0);
        if (has_next) {
            uint16_t* na = (uint16_t*)(sm + (ib ^ 1) * NN_BUF_B);
            uint16_t* nb = (uint16_t*)(sm + (ib ^ 1) * NN_BUF_B + 2 * TN_TILE_B);
            stage_tn(na, na + TN_TILE_B / 2, fa, tid);
            stage_nn_b(nb, nb + NN_BT_B / 2, fb, tid);
        }
        __syncthreads();
    }
    epilogue_store(c, tmp, nullptr, 256, b * 512 + m0, n0, mrow0, ncol0, lane);
}

// ---------------------------------------------------------------------------
// Attention: tensor-pipe scores from PRE-SPLIT bf16 q/k (pure-copy staging),
// interleaved dual-query exact sparsemax.
// ---------------------------------------------------------------------------
#define SC_STR 522
#define AK_OFF   0
#define AKL_OFF  20480
#define AQ_OFF   40960
#define AQL_OFF  43520
#define ASC_OFF  46080
#define ATTN_SMEM_BYTES (46080 + 32 * SC_STR * 4)   // 112896

__global__ __launch_bounds__(512, 2) void attn_sparsemax_kernel(float* __restrict__ avg)
{
    extern __shared__ __align__(16) char sm[];
    uint16_t* Khi = (uint16_t*)(sm + AK_OFF);
    uint16_t* Klo = (uint16_t*)(sm + AKL_OFF);
    uint16_t* Qhi = (uint16_t*)(sm + AQ_OFF);
    uint16_t* Qlo = (uint16_t*)(sm + AQL_OFF);
    float*    Ssc = (float*)(sm + ASC_OFF);

    const int tid  = threadIdx.x;
    const int lane = tid & 31, w = tid >> 5;
    const int b    = blockIdx.x >> 4;
    const int s0   = (blockIdx.x & 15) << 5;

    const uint16_t* qkh = g_qkh + (size_t)b * 512 * 512;
    const uint16_t* qkl = g_qkl + (size_t)b * 512 * 512;

    float acc[2][16];
#pragma unroll
    for (int qi = 0; qi < 2; ++qi)
#pragma unroll
        for (int i = 0; i < 16; ++i) acc[qi][i] = 0.f;

    const int lr = lane & 7, lg = lane >> 3;

    for (int h = 0; h < HH; ++h) {
        __syncthreads();

        // ---- stage Q (32 x 32) hi/lo: pure copy ----
        if (tid < 256) {
            int r = (tid & 127) >> 2, e8 = (tid & 3) * 8;
            const uint16_t* src = (tid < 128 ? qkh : qkl);
            uint16_t* dst = (tid < 128 ? Qhi : Qlo);
            *(uint4*)(dst + r * AT_STR + e8) =
                *(const uint4*)(src + (size_t)(s0 + r) * 512 + h * 32 + e8);
        }

#pragma unroll
        for (int ck = 0; ck < 2; ++ck) {
            if (ck) __syncthreads();
            // ---- stage K chunk (256 x 32) hi/lo: pure copy ----
            {
                int r = tid >> 1, e16 = (tid & 1) * 16;
                size_t gofs = (size_t)(ck * 256 + r) * 512 + 256 + h * 32 + e16;
                *(uint4*)(Khi + r * AT_STR + e16)     = *(const uint4*)(qkh + gofs);
                *(uint4*)(Khi + r * AT_STR + e16 + 8) = *(const uint4*)(qkh + gofs + 8);
                *(uint4*)(Klo + r * AT_STR + e16)     = *(const uint4*)(qkl + gofs);
                *(uint4*)(Klo + r * AT_STR + e16 + 8) = *(const uint4*)(qkl + gofs + 8);
            }
            __syncthreads();

            float c[2][2][4];
#pragma unroll
            for (int mi = 0; mi < 2; ++mi)
#pragma unroll
                for (int hf = 0; hf < 2; ++hf)
#pragma unroll
                    for (int q = 0; q < 4; ++q) c[mi][hf][q] = 0.f;

#pragma unroll
            for (int k16 = 0; k16 < 32; k16 += 16) {
                uint32_t aoff = (uint32_t)(((lane & 15) * AT_STR + k16 + ((lane >> 4) << 3)) * 2);
                uint32_t ah[2][4], al[2][4];
#pragma unroll
                for (int mi = 0; mi < 2; ++mi) {
                    ldmx4(ah[mi], cvta_s(Qhi) + aoff + mi * (16 * AT_STR * 2));
                    ldmx4(al[mi], cvta_s(Qlo) + aoff + mi * (16 * AT_STR * 2));
                }
                uint32_t boff = (uint32_t)(((w * 16 + lr + ((lg & 2) << 2)) * AT_STR
                                            + k16 + ((lg & 1) << 3)) * 2);
                uint32_t bh[4], bl[4];
                ldmx4(bh, cvta_s(Khi) + boff);
                ldmx4(bl, cvta_s(Klo) + boff);
#pragma unroll
                for (int mi = 0; mi < 2; ++mi)
#pragma unroll
                    for (int hf = 0; hf < 2; ++hf) {
                        float* cc = c[mi][hf];
                        mma16816(cc, ah[mi], bh[hf * 2], bh[hf * 2 + 1]);
                        mma16816(cc, ah[mi], bl[hf * 2], bl[hf * 2 + 1]);
                        mma16816(cc, al[mi], bh[hf * 2], bh[hf * 2 + 1]);
                    }
            }

#pragma unroll
            for (int mi = 0; mi < 2; ++mi)
#pragma unroll
                for (int hf = 0; hf < 2; ++hf) {
                    int gc = ck * 256 + w * 16 + hf * 8 + ((lane & 3) << 1);
                    int r0 = mi * 16 + (lane >> 2);
                    int r1 = r0 + 8;
                    float v0 = c[mi][hf][0] * 0.17677669529663687f;
                    float v1 = c[mi][hf][1] * 0.17677669529663687f;
                    float v2 = c[mi][hf][2] * 0.17677669529663687f;
                    float v3 = c[mi][hf][3] * 0.17677669529663687f;
                    if (gc     == s0 + r0) v0 = -CUDART_INF_F;
                    if (gc + 1 == s0 + r0) v1 = -CUDART_INF_F;
                    if (gc     == s0 + r1) v2 = -CUDART_INF_F;
                    if (gc + 1 == s0 + r1) v3 = -CUDART_INF_F;
                    *(float2*)&Ssc[r0 * SC_STR + gc] = make_float2(v0, v1);
                    *(float2*)&Ssc[r1 * SC_STR + gc] = make_float2(v2, v3);
                }
        }
        __syncthreads();

        // ---- dual-query exact sparsemax (Michelot), interleaved ----
        float zz0[16], zz1[16];
        {
            int q0 = w * 2, q1 = w * 2 + 1;
#pragma unroll
            for (int i = 0; i < 16; ++i) {
                zz0[i] = Ssc[q0 * SC_STR + lane + 32 * i];
                zz1[i] = Ssc[q1 * SC_STR + lane + 32 * i];
            }
        }
        float tau0 = -CUDART_INF_F, tau1 = -CUDART_INF_F;
        int prev0 = -1, prev1 = -1;
        bool done0 = false, done1 = false;
        for (int it = 0; it < 64; ++it) {
            float sa0 = 0.f, sa1 = 0.f;
            int ca0 = 0, ca1 = 0;
#pragma unroll
            for (int i = 0; i < 16; ++i) {
                if (zz0[i] > tau0) { sa0 += zz0[i]; ca0++; }
                if (zz1[i] > tau1) { sa1 += zz1[i]; ca1++; }
            }
#pragma unroll
            for (int o = 16; o; o >>= 1) {
                sa0 += __shfl_xor_sync(0xffffffffu, sa0, o);
                sa1 += __shfl_xor_sync(0xffffffffu, sa1, o);
            }
            ca0 = __reduce_add_sync(0xffffffffu, ca0);
            ca1 = __reduce_add_sync(0xffffffffu, ca1);
            if (!done0) {
                if (ca0 == prev0 || ca0 == 0) done0 = true;
                else { prev0 = ca0; tau0 = (sa0 - 1.0f) / (float)ca0; }
            }
            if (!done1) {
                if (ca1 == prev1 || ca1 == 0) done1 = true;
                else { prev1 = ca1; tau1 = (sa1 - 1.0f) / (float)ca1; }
            }
            if (done0 && done1) break;
        }
#pragma unroll
        for (int i = 0; i < 16; ++i) {
            acc[0][i] += fmaxf(zz0[i] - tau0, 0.f) * 0.125f;
            acc[1][i] += fmaxf(zz1[i] - tau1, 0.f) * 0.125f;
        }
    }

#pragma unroll
    for (int qi = 0; qi < 2; ++qi) {
        float* dst = avg + (size_t)(b * 512 + s0 + w * 2 + qi) * 512;
#pragma unroll
        for (int i = 0; i < 16; ++i) dst[lane + 32 * i] = acc[qi][i];
    }
}

// ---------------------------------------------------------------------------
extern "C" void kernel_launch(void* const* d_in, const int* in_sizes, int n_in,
                              void* d_out, int out_size)
{
    const float* x  = (const float*)d_in[0];
    const float* Wq = (const float*)d_in[1];
    const float* bq = (const float*)d_in[2];
    const float* Wk = (const float*)d_in[3];
    const float* bk = (const float*)d_in[4];
    const float* Wv = (const float*)d_in[5];
    const float* bv = (const float*)d_in[6];
    const float* Wo = (const float*)d_in[7];
    const float* bo = (const float*)d_in[8];

    float* out = (float*)d_out;                        // [32,512,256]
    float* avg = out + (size_t)NROWS * DD;             // [32,512,512]

    float* tmp = nullptr;
    cudaGetSymbolAddress((void**)&tmp, g_tmp);

    cudaFuncSetAttribute(mma_qkv, cudaFuncAttributeMaxDynamicSharedMemorySize, TN_SMEM_B);
    cudaFuncSetAttribute(mma_out, cudaFuncAttributeMaxDynamicSharedMemorySize, TN_SMEM_B);
    cudaFuncSetAttribute(mma_nn,  cudaFuncAttributeMaxDynamicSharedMemorySize, NN_SMEM_B);
    cudaFuncSetAttribute(attn_sparsemax_kernel,
                         cudaFuncAttributeMaxDynamicSharedMemorySize, ATTN_SMEM_BYTES);

    // 1) QKV projections: q,k -> bf16 hi/lo (pre-split); v -> fp32 g_v
    {
        dim3 grid(6, 128);
        mma_qkv<<<grid, 256, TN_SMEM_B>>>(x, Wq, bq, Wk, bk, Wv, bv);
    }

    // 2) scores (HMMA) + sparsemax + head average -> avg_attention (in d_out)
    attn_sparsemax_kernel<<<NROWS / 32, 512, ATTN_SMEM_BYTES>>>(avg);

    // 3) tmp[b] = avg[b] @ v[b]
    {
        dim3 grid(2, 4, BB);
        mma_nn<<<grid, 256, NN_SMEM_B>>>(avg, tmp);
    }

    // 4) out = tmp @ Wo^T + bo
    {
        dim3 grid(2, 128);
        mma_out<<<grid, 256, TN_SMEM_B>>>(Wo, bo, out);
    }
}

// round 15
// speedup vs baseline: 1.5852x; 1.0894x over previous
#include <cuda_runtime.h>
#include <cuda_bf16.h>
#include <cstdint>
#include <math.h>
#include <math_constants.h>

// Problem constants
#define BB 32
#define SS 512
#define DD 256
#define HH 8
#define DHH 32
#define NROWS (BB*SS)

// Scratch (__device__ globals; allocation is banned)
__device__ uint16_t g_qkh[(size_t)NROWS * 512];   // bf16 hi: [row][0:256)=q, [256:512)=k
__device__ uint16_t g_qkl[(size_t)NROWS * 512];   // bf16 lo
__device__ float    g_v[(size_t)NROWS * 256];     // v fp32  [b*512+t][e]
__device__ float    g_tmp[(size_t)NROWS * 256];   // avg @ v result

// ---------------------------------------------------------------------------
// bf16 split + pack helpers (3xBF16 fp32 emulation)
// ---------------------------------------------------------------------------
__device__ __forceinline__ void splitpk(float x, float y, uint32_t& h, uint32_t& l) {
    __nv_bfloat16 hx = __float2bfloat16(x), hy = __float2bfloat16(y);
    float rx = x - __bfloat162float(hx);
    float ry = y - __bfloat162float(hy);
    __nv_bfloat16 lx = __float2bfloat16(rx), ly = __float2bfloat16(ry);
    h = (uint32_t)__bfloat16_as_ushort(hx) | ((uint32_t)__bfloat16_as_ushort(hy) << 16);
    l = (uint32_t)__bfloat16_as_ushort(lx) | ((uint32_t)__bfloat16_as_ushort(ly) << 16);
}

__device__ __forceinline__ uint32_t cvta_s(const void* p) {
    return (uint32_t)__cvta_generic_to_shared(p);
}

__device__ __forceinline__ void ldmx4(uint32_t r[4], uint32_t addr) {
    asm volatile("ldmatrix.sync.aligned.m8n8.x4.shared.b16 {%0,%1,%2,%3}, [%4];"
                 : "=r"(r[0]), "=r"(r[1]), "=r"(r[2]), "=r"(r[3]) : "r"(addr));
}
__device__ __forceinline__ void ldmx4t(uint32_t r[4], uint32_t addr) {
    asm volatile("ldmatrix.sync.aligned.m8n8.x4.trans.shared.b16 {%0,%1,%2,%3}, [%4];"
                 : "=r"(r[0]), "=r"(r[1]), "=r"(r[2]), "=r"(r[3]) : "r"(addr));
}

__device__ __forceinline__ void mma16816(float c[4], const uint32_t a[4],
                                         uint32_t b0, uint32_t b1) {
    asm volatile(
        "mma.sync.aligned.m16n8k16.row.col.f32.bf16.bf16.f32 "
        "{%0,%1,%2,%3}, {%4,%5,%6,%7}, {%8,%9}, {%0,%1,%2,%3};"
        : "+f"(c[0]), "+f"(c[1]), "+f"(c[2]), "+f"(c[3])
        : "r"(a[0]), "r"(a[1]), "r"(a[2]), "r"(a[3]), "r"(b0), "r"(b1));
}

// ---------------------------------------------------------------------------
// Tile strides
// ---------------------------------------------------------------------------
#define AT_STR 40    // K-major tiles: 32 k + 8 pad
#define BN_STR 136   // NN B tile [k][n]: 128 n + 8 pad

#define TN_TILE_B  (128 * AT_STR * 2)            // 10240
#define TN_BUF_B   (4 * TN_TILE_B)               // 40960
#define TN_SMEM_B  (2 * TN_BUF_B)                // 81920

#define NN_BT_B    (32 * BN_STR * 2)             // 8704
#define NN_BUF_B   (2 * TN_TILE_B + 2 * NN_BT_B) // 37888
#define NN_SMEM_B  (2 * NN_BUF_B)                // 75776

// Stage a 128x32 fp32 K-contig tile -> hi/lo bf16 smem (row stride AT_STR)
__device__ __forceinline__ void stage_tn(uint16_t* hi, uint16_t* lo,
                                         const float4 f[4], int tid) {
    int row = tid >> 1, kh = (tid & 1) * 16;
    uint4 H0, H1, L0, L1;
    splitpk(f[0].x, f[0].y, H0.x, L0.x); splitpk(f[0].z, f[0].w, H0.y, L0.y);
    splitpk(f[1].x, f[1].y, H0.z, L0.z); splitpk(f[1].z, f[1].w, H0.w, L0.w);
    splitpk(f[2].x, f[2].y, H1.x, L1.x); splitpk(f[2].z, f[2].w, H1.y, L1.y);
    splitpk(f[3].x, f[3].y, H1.z, L1.z); splitpk(f[3].z, f[3].w, H1.w, L1.w);
    *(uint4*)(hi + row * AT_STR + kh)     = H0;
    *(uint4*)(hi + row * AT_STR + kh + 8) = H1;
    *(uint4*)(lo + row * AT_STR + kh)     = L0;
    *(uint4*)(lo + row * AT_STR + kh + 8) = L1;
}

// Stage a 32x128 fp32 N-contig tile -> hi/lo bf16 smem [k][n] (stride BN_STR)
__device__ __forceinline__ void stage_nn_b(uint16_t* hi, uint16_t* lo,
                                           const float4 f[4], int tid) {
    int k = tid >> 3, nq = (tid & 7) * 16;
    uint4 H0, H1, L0, L1;
    splitpk(f[0].x, f[0].y, H0.x, L0.x); splitpk(f[0].z, f[0].w, H0.y, L0.y);
    splitpk(f[1].x, f[1].y, H0.z, L0.z); splitpk(f[1].z, f[1].w, H0.w, L0.w);
    splitpk(f[2].x, f[2].y, H1.x, L1.x); splitpk(f[2].z, f[2].w, H1.y, L1.y);
    splitpk(f[3].x, f[3].y, H1.z, L1.z); splitpk(f[3].z, f[3].w, H1.w, L1.w);
    *(uint4*)(hi + k * BN_STR + nq)     = H0;
    *(uint4*)(hi + k * BN_STR + nq + 8) = H1;
    *(uint4*)(lo + k * BN_STR + nq)     = L0;
    *(uint4*)(lo + k * BN_STR + nq + 8) = L1;
}

// Warp-level K-chunk compute: 64x32 warp tile, 3-pass split.
// Pass-outermost ordering: 16 independent MMAs per pass (reuse distance 16).
template<bool TRANSB>
__device__ __forceinline__ void compute_chunk(
    float c[4][4][4],
    const uint16_t* sAhi, const uint16_t* sAlo,
    const uint16_t* sBhi, const uint16_t* sBlo,
    int lane, int mrow0, int ncol0)
{
    const int lr = lane & 7, lg = lane >> 3;
#pragma unroll
    for (int k16 = 0; k16 < 32; k16 += 16) {
        uint32_t ah[4][4], al[4][4];
        uint32_t aoff = (uint32_t)(((mrow0 + (lane & 15)) * AT_STR + k16 + ((lane >> 4) << 3)) * 2);
#pragma unroll
        for (int mi = 0; mi < 4; ++mi) {
            ldmx4(ah[mi], cvta_s(sAhi) + aoff + mi * (16 * AT_STR * 2));
            ldmx4(al[mi], cvta_s(sAlo) + aoff + mi * (16 * AT_STR * 2));
        }
        uint32_t bh[2][4], bl[2][4];
#pragma unroll
        for (int nb = 0; nb < 2; ++nb) {
            uint32_t boff;
            if (TRANSB) {
                boff = (uint32_t)(((k16 + lr + ((lg & 1) << 3)) * BN_STR
                                   + ncol0 + nb * 16 + ((lg & 2) << 2)) * 2);
                ldmx4t(bh[nb], cvta_s(sBhi) + boff);
                ldmx4t(bl[nb], cvta_s(sBlo) + boff);
            } else {
                boff = (uint32_t)(((ncol0 + nb * 16 + lr + ((lg & 2) << 2)) * AT_STR
                                   + k16 + ((lg & 1) << 3)) * 2);
                ldmx4(bh[nb], cvta_s(sBhi) + boff);
                ldmx4(bl[nb], cvta_s(sBlo) + boff);
            }
        }
#pragma unroll
        for (int pass = 0; pass < 3; ++pass)
#pragma unroll
            for (int mi = 0; mi < 4; ++mi)
#pragma unroll
                for (int nb = 0; nb < 2; ++nb)
#pragma unroll
                    for (int half = 0; half < 2; ++half) {
                        float* cc = c[mi][nb * 2 + half];
                        const uint32_t* aa = (pass == 2) ? al[mi] : ah[mi];
                        uint32_t b0 = (pass == 1) ? bl[nb][half * 2]     : bh[nb][half * 2];
                        uint32_t b1 = (pass == 1) ? bl[nb][half * 2 + 1] : bh[nb][half * 2 + 1];
                        mma16816(cc, aa, b0, b1);
                    }
    }
}

__device__ __forceinline__ void epilogue_store(
    float c[4][4][4], float* __restrict__ C, const float* __restrict__ bias,
    int ldc, int m0, int cn0, int mrow0, int ncol0, int lane)
{
#pragma unroll
    for (int mi = 0; mi < 4; ++mi) {
        int r = m0 + mrow0 + mi * 16 + (lane >> 2);
#pragma unroll
        for (int ni = 0; ni < 4; ++ni) {
            int cl = ncol0 + ni * 8 + ((lane & 3) << 1);
            float b0 = 0.f, b1 = 0.f;
            if (bias) { b0 = bias[cl]; b1 = bias[cl + 1]; }
            float2 v0 = make_float2(c[mi][ni][0] + b0, c[mi][ni][1] + b1);
            float2 v1 = make_float2(c[mi][ni][2] + b0, c[mi][ni][3] + b1);
            *(float2*)(C + (size_t)r * ldc + cn0 + cl) = v0;
            *(float2*)(C + (size_t)(r + 8) * ldc + cn0 + cl) = v1;
        }
    }
}

// Split epilogue: write q/k as bf16 hi/lo into g_qkh/g_qkl (row len 512)
__device__ __forceinline__ void epilogue_split(
    float c[4][4][4], const float* __restrict__ bias,
    int m0, int zbase, int mrow0, int ncol0, int lane)
{
#pragma unroll
    for (int mi = 0; mi < 4; ++mi) {
        int r = m0 + mrow0 + mi * 16 + (lane >> 2);
#pragma unroll
        for (int ni = 0; ni < 4; ++ni) {
            int cl = ncol0 + ni * 8 + ((lane & 3) << 1);
            float b0 = bias[cl], b1 = bias[cl + 1];
            uint32_t h0, l0, h1, l1;
            splitpk(c[mi][ni][0] + b0, c[mi][ni][1] + b1, h0, l0);
            splitpk(c[mi][ni][2] + b0, c[mi][ni][3] + b1, h1, l1);
            size_t o0 = (size_t)r * 512 + zbase + cl;
            size_t o1 = (size_t)(r + 8) * 512 + zbase + cl;
            *(uint32_t*)(g_qkh + o0) = h0;
            *(uint32_t*)(g_qkl + o0) = l0;
            *(uint32_t*)(g_qkh + o1) = h1;
            *(uint32_t*)(g_qkl + o1) = l1;
        }
    }
}

// ---------------------------------------------------------------------------
// TN GEMM body — 256 threads, 8 warps (2x4), double-buffered.
// ---------------------------------------------------------------------------
__device__ __forceinline__ void gemm_tn_mma_body(
    char* sm, float c[4][4][4],
    const float* __restrict__ A, const float* __restrict__ B,
    int K, int lda, int ldb, int m0, int lane, int mrow0, int ncol0)
{
    const int tid = threadIdx.x;
    const int row = tid >> 1, kh = (tid & 1) * 16;

    const float* pA = A + (size_t)(m0 + row) * lda + kh;
    const float* pB = B + (size_t)row * ldb + kh;

    float4 fa[4], fb[4];
#pragma unroll
    for (int i = 0; i < 4; ++i) {
        fa[i] = *(const float4*)(pA + i * 4);
        fb[i] = *(const float4*)(pB + i * 4);
    }
    {
        uint16_t* b0 = (uint16_t*)sm;
        stage_tn(b0,             b0 + TN_TILE_B / 2,     fa, tid);
        stage_tn(b0 + TN_TILE_B, b0 + 3 * TN_TILE_B / 2, fb, tid);
    }
    __syncthreads();

    int ib = 0;
    for (int k0 = 0; k0 < K; k0 += 32, ib ^= 1) {
        const bool has_next = (k0 + 32 < K);
        if (has_next) {
#pragma unroll
            for (int i = 0; i < 4; ++i) {
                fa[i] = *(const float4*)(pA + k0 + 32 + i * 4);
                fb[i] = *(const float4*)(pB + k0 + 32 + i * 4);
            }
        }
        uint16_t* cur = (uint16_t*)(sm + ib * TN_BUF_B);
        compute_chunk<false>(c, cur, cur + TN_TILE_B / 2,
                             cur + TN_TILE_B, cur + 3 * TN_TILE_B / 2,
                             lane, mrow0, ncol0);
        if (has_next) {
            uint16_t* nxt = (uint16_t*)(sm + (ib ^ 1) * TN_BUF_B);
            stage_tn(nxt,             nxt + TN_TILE_B / 2,     fa, tid);
            stage_tn(nxt + TN_TILE_B, nxt + 3 * TN_TILE_B / 2, fb, tid);
        }
        __syncthreads();
    }
}

__global__ __launch_bounds__(256) void mma_qkv(
    const float* __restrict__ x,
    const float* __restrict__ Wq, const float* __restrict__ bq,
    const float* __restrict__ Wk, const float* __restrict__ bk,
    const float* __restrict__ Wv, const float* __restrict__ bv)
{
    extern __shared__ __align__(16) char sm[];
    const int tid = threadIdx.x, lane = tid & 31, warp = tid >> 5;
    const int mrow0 = (warp & 1) * 64, ncol0 = (warp >> 1) * 32;
    const int z = blockIdx.x;
    const int m0 = blockIdx.y * 128;
    const float* B; const float* bias;
    if (z < 2)      { B = Wq + (size_t)z * 128 * 256;       bias = bq + z * 128; }
    else if (z < 4) { B = Wk + (size_t)(z - 2) * 128 * 256; bias = bk + (z - 2) * 128; }
    else            { B = Wv + (size_t)(z - 4) * 128 * 256; bias = bv + (z - 4) * 128; }

    float c[4][4][4];
#pragma unroll
    for (int i = 0; i < 4; ++i)
#pragma unroll
        for (int j = 0; j < 4; ++j)
#pragma unroll
            for (int q = 0; q < 4; ++q) c[i][j][q] = 0.f;

    gemm_tn_mma_body(sm, c, x, B, 256, 256, 256, m0, lane, mrow0, ncol0);

    if (z < 4) epilogue_split(c, bias, m0, z * 128, mrow0, ncol0, lane);
    else       epilogue_store(c, g_v, bias, 256, m0, (z - 4) * 128, mrow0, ncol0, lane);
}

__global__ __launch_bounds__(256) void mma_out(
    const float* __restrict__ Wo, const float* __restrict__ bo,
    float* __restrict__ out)
{
    extern __shared__ __align__(16) char sm[];
    const int tid = threadIdx.x, lane = tid & 31, warp = tid >> 5;
    const int mrow0 = (warp & 1) * 64, ncol0 = (warp >> 1) * 32;
    const int n0 = blockIdx.x * 128;
    const int m0 = blockIdx.y * 128;

    float c[4][4][4];
#pragma unroll
    for (int i = 0; i < 4; ++i)
#pragma unroll
        for (int j = 0; j < 4; ++j)
#pragma unroll
            for (int q = 0; q < 4; ++q) c[i][j][q] = 0.f;

    gemm_tn_mma_body(sm, c, g_tmp, Wo + (size_t)n0 * 256, 256, 256, 256, m0,
                     lane, mrow0, ncol0);
    epilogue_store(c, out, bo + n0, 256, m0, n0, mrow0, ncol0, lane);
}

// ---------------------------------------------------------------------------
// NN batched (double-buffered): tmp[b] = avg[b] @ v[b]   (v from g_v, ldb=256)
// ---------------------------------------------------------------------------
__global__ __launch_bounds__(256) void mma_nn(
    const float* __restrict__ avg, float* __restrict__ tmp)
{
    extern __shared__ __align__(16) char sm[];
    const int tid = threadIdx.x;
    const int lane = tid & 31, warp = tid >> 5;
    const int mrow0 = (warp & 1) * 64, ncol0 = (warp >> 1) * 32;
    const int n0 = blockIdx.x * 128;
    const int m0 = blockIdx.y * 128;
    const int b  = blockIdx.z;

    const float* A = avg + (size_t)b * 512 * 512;
    const float* B = g_v + (size_t)b * 512 * 256;

    float c[4][4][4];
#pragma unroll
    for (int i = 0; i < 4; ++i)
#pragma unroll
        for (int j = 0; j < 4; ++j)
#pragma unroll
            for (int q = 0; q < 4; ++q) c[i][j][q] = 0.f;

    const int row = tid >> 1, kh = (tid & 1) * 16;
    const int bk = tid >> 3, bn = (tid & 7) * 16;
    const float* pA = A + (size_t)(m0 + row) * 512 + kh;
    const float* pB = B + n0 + bn;

    float4 fa[4], fb[4];
#pragma unroll
    for (int i = 0; i < 4; ++i) {
        fa[i] = *(const float4*)(pA + i * 4);
        fb[i] = *(const float4*)(pB + (size_t)bk * 256 + i * 4);
    }
    {
        uint16_t* a0 = (uint16_t*)sm;
        uint16_t* b0 = (uint16_t*)(sm + 2 * TN_TILE_B);
        stage_tn(a0, a0 + TN_TILE_B / 2, fa, tid);
        stage_nn_b(b0, b0 + NN_BT_B / 2, fb, tid);
    }
    __syncthreads();

    int ib = 0;
    for (int k0 = 0; k0 < 512; k0 += 32, ib ^= 1) {
        const bool has_next = (k0 + 32 < 512);
        if (has_next) {
#pragma unroll
            for (int i = 0; i < 4; ++i) {
                fa[i] = *(const float4*)(pA + k0 + 32 + i * 4);
                fb[i] = *(const float4*)(pB + (size_t)(k0 + 32 + bk) * 256 + i * 4);
            }
        }
        uint16_t* ca = (uint16_t*)(sm + ib * NN_BUF_B);
        uint16_t* cb = (uint16_t*)(sm + ib * NN_BUF_B + 2 * TN_TILE_B);
        compute_chunk<true>(c, ca, ca + TN_TILE_B / 2, cb, cb + NN_BT_B / 2,
                            lane, mrow0, ncol0);
        if (has_next) {
            uint16_t* na = (uint16_t*)(sm + (ib ^ 1) * NN_BUF_B);
            uint16_t* nb = (uint16_t*)(sm + (ib ^ 1) * NN_BUF_B + 2 * TN_TILE_B);
            stage_tn(na, na + TN_TILE_B / 2, fa, tid);
            stage_nn_b(nb, nb + NN_BT_B / 2, fb, tid);
        }
        __syncthreads();
    }
    epilogue_store(c, tmp, nullptr, 256, b * 512 + m0, n0, mrow0, ncol0, lane);
}

// ---------------------------------------------------------------------------
// Attention: tensor-pipe scores from pre-split bf16 q/k, interleaved
// dual-query exact sparsemax with zmax-1 tau init.
// ---------------------------------------------------------------------------
#define SC_STR 522
#define AK_OFF   0
#define AKL_OFF  20480
#define AQ_OFF   40960
#define AQL_OFF  43520
#define ASC_OFF  46080
#define ATTN_SMEM_BYTES (46080 + 32 * SC_STR * 4)   // 112896

__global__ __launch_bounds__(512, 2) void attn_sparsemax_kernel(float* __restrict__ avg)
{
    extern __shared__ __align__(16) char sm[];
    uint16_t* Khi = (uint16_t*)(sm + AK_OFF);
    uint16_t* Klo = (uint16_t*)(sm + AKL_OFF);
    uint16_t* Qhi = (uint16_t*)(sm + AQ_OFF);
    uint16_t* Qlo = (uint16_t*)(sm + AQL_OFF);
    float*    Ssc = (float*)(sm + ASC_OFF);

    const int tid  = threadIdx.x;
    const int lane = tid & 31, w = tid >> 5;
    const int b    = blockIdx.x >> 4;
    const int s0   = (blockIdx.x & 15) << 5;

    const uint16_t* qkh = g_qkh + (size_t)b * 512 * 512;
    const uint16_t* qkl = g_qkl + (size_t)b * 512 * 512;

    float acc[2][16];
#pragma unroll
    for (int qi = 0; qi < 2; ++qi)
#pragma unroll
        for (int i = 0; i < 16; ++i) acc[qi][i] = 0.f;

    const int lr = lane & 7, lg = lane >> 3;

    for (int h = 0; h < HH; ++h) {
        __syncthreads();

        // ---- stage Q (32 x 32) hi/lo: pure copy ----
        if (tid < 256) {
            int r = (tid & 127) >> 2, e8 = (tid & 3) * 8;
            const uint16_t* src = (tid < 128 ? qkh : qkl);
            uint16_t* dst = (tid < 128 ? Qhi : Qlo);
            *(uint4*)(dst + r * AT_STR + e8) =
                *(const uint4*)(src + (size_t)(s0 + r) * 512 + h * 32 + e8);
        }

#pragma unroll
        for (int ck = 0; ck < 2; ++ck) {
            if (ck) __syncthreads();
            // ---- stage K chunk (256 x 32) hi/lo: pure copy ----
            {
                int r = tid >> 1, e16 = (tid & 1) * 16;
                size_t gofs = (size_t)(ck * 256 + r) * 512 + 256 + h * 32 + e16;
                *(uint4*)(Khi + r * AT_STR + e16)     = *(const uint4*)(qkh + gofs);
                *(uint4*)(Khi + r * AT_STR + e16 + 8) = *(const uint4*)(qkh + gofs + 8);
                *(uint4*)(Klo + r * AT_STR + e16)     = *(const uint4*)(qkl + gofs);
                *(uint4*)(Klo + r * AT_STR + e16 + 8) = *(const uint4*)(qkl + gofs + 8);
            }
            __syncthreads();

            float c[2][2][4];
#pragma unroll
            for (int mi = 0; mi < 2; ++mi)
#pragma unroll
                for (int hf = 0; hf < 2; ++hf)
#pragma unroll
                    for (int q = 0; q < 4; ++q) c[mi][hf][q] = 0.f;

#pragma unroll
            for (int k16 = 0; k16 < 32; k16 += 16) {
                uint32_t aoff = (uint32_t)(((lane & 15) * AT_STR + k16 + ((lane >> 4) << 3)) * 2);
                uint32_t ah[2][4], al[2][4];
#pragma unroll
                for (int mi = 0; mi < 2; ++mi) {
                    ldmx4(ah[mi], cvta_s(Qhi) + aoff + mi * (16 * AT_STR * 2));
                    ldmx4(al[mi], cvta_s(Qlo) + aoff + mi * (16 * AT_STR * 2));
                }
                uint32_t boff = (uint32_t)(((w * 16 + lr + ((lg & 2) << 2)) * AT_STR
                                            + k16 + ((lg & 1) << 3)) * 2);
                uint32_t bh[4], bl[4];
                ldmx4(bh, cvta_s(Khi) + boff);
                ldmx4(bl, cvta_s(Klo) + boff);
#pragma unroll
                for (int pass = 0; pass < 3; ++pass)
#pragma unroll
                    for (int mi = 0; mi < 2; ++mi)
#pragma unroll
                        for (int hf = 0; hf < 2; ++hf) {
                            float* cc = c[mi][hf];
                            const uint32_t* aa = (pass == 2) ? al[mi] : ah[mi];
                            uint32_t b0 = (pass == 1) ? bl[hf * 2]     : bh[hf * 2];
                            uint32_t b1 = (pass == 1) ? bl[hf * 2 + 1] : bh[hf * 2 + 1];
                            mma16816(cc, aa, b0, b1);
                        }
            }

#pragma unroll
            for (int mi = 0; mi < 2; ++mi)
#pragma unroll
                for (int hf = 0; hf < 2; ++hf) {
                    int gc = ck * 256 + w * 16 + hf * 8 + ((lane & 3) << 1);
                    int r0 = mi * 16 + (lane >> 2);
                    int r1 = r0 + 8;
                    float v0 = c[mi][hf][0] * 0.17677669529663687f;
                    float v1 = c[mi][hf][1] * 0.17677669529663687f;
                    float v2 = c[mi][hf][2] * 0.17677669529663687f;
                    float v3 = c[mi][hf][3] * 0.17677669529663687f;
                    if (gc     == s0 + r0) v0 = -CUDART_INF_F;
                    if (gc + 1 == s0 + r0) v1 = -CUDART_INF_F;
                    if (gc     == s0 + r1) v2 = -CUDART_INF_F;
                    if (gc + 1 == s0 + r1) v3 = -CUDART_INF_F;
                    *(float2*)&Ssc[r0 * SC_STR + gc] = make_float2(v0, v1);
                    *(float2*)&Ssc[r1 * SC_STR + gc] = make_float2(v2, v3);
                }
        }
        __syncthreads();

        // ---- dual-query exact sparsemax (Michelot), tau0 = zmax - 1 ----
        float zz0[16], zz1[16];
        {
            int q0 = w * 2, q1 = w * 2 + 1;
#pragma unroll
            for (int i = 0; i < 16; ++i) {
                zz0[i] = Ssc[q0 * SC_STR + lane + 32 * i];
                zz1[i] = Ssc[q1 * SC_STR + lane + 32 * i];
            }
        }
        float m0v = -CUDART_INF_F, m1v = -CUDART_INF_F;
#pragma unroll
        for (int i = 0; i < 16; ++i) {
            m0v = fmaxf(m0v, zz0[i]);
            m1v = fmaxf(m1v, zz1[i]);
        }
#pragma unroll
        for (int o = 16; o; o >>= 1) {
            m0v = fmaxf(m0v, __shfl_xor_sync(0xffffffffu, m0v, o));
            m1v = fmaxf(m1v, __shfl_xor_sync(0xffffffffu, m1v, o));
        }
        // tau* >= zmax - 1 always (equality iff support = 1) -> valid start.
        float tau0 = m0v - 1.0f, tau1 = m1v - 1.0f;
        int prev0 = -1, prev1 = -1;
        bool done0 = false, done1 = false;
        for (int it = 0; it < 64; ++it) {
            float sa0 = 0.f, sa1 = 0.f;
            int ca0 = 0, ca1 = 0;
#pragma unroll
            for (int i = 0; i < 16; ++i) {
                if (zz0[i] > tau0) { sa0 += zz0[i]; ca0++; }
                if (zz1[i] > tau1) { sa1 += zz1[i]; ca1++; }
            }
#pragma unroll
            for (int o = 16; o; o >>= 1) {
                sa0 += __shfl_xor_sync(0xffffffffu, sa0, o);
                sa1 += __shfl_xor_sync(0xffffffffu, sa1, o);
            }
            ca0 = __reduce_add_sync(0xffffffffu, ca0);
            ca1 = __reduce_add_sync(0xffffffffu, ca1);
            if (!done0) {
                if (ca0 == prev0 || ca0 == 0) done0 = true;
                else { prev0 = ca0; tau0 = (sa0 - 1.0f) / (float)ca0; }
            }
            if (!done1) {
                if (ca1 == prev1 || ca1 == 0) done1 = true;
                else { prev1 = ca1; tau1 = (sa1 - 1.0f) / (float)ca1; }
            }
            if (done0 && done1) break;
        }
#pragma unroll
        for (int i = 0; i < 16; ++i) {
            acc[0][i] += fmaxf(zz0[i] - tau0, 0.f) * 0.125f;
            acc[1][i] += fmaxf(zz1[i] - tau1, 0.f) * 0.125f;
        }
    }

#pragma unroll
    for (int qi = 0; qi < 2; ++qi) {
        float* dst = avg + (size_t)(b * 512 + s0 + w * 2 + qi) * 512;
#pragma unroll
        for (int i = 0; i < 16; ++i) dst[lane + 32 * i] = acc[qi][i];
    }
}

// ---------------------------------------------------------------------------
extern "C" void kernel_launch(void* const* d_in, const int* in_sizes, int n_in,
                              void* d_out, int out_size)
{
    const float* x  = (const float*)d_in[0];
    const float* Wq = (const float*)d_in[1];
    const float* bq = (const float*)d_in[2];
    const float* Wk = (const float*)d_in[3];
    const float* bk = (const float*)d_in[4];
    const float* Wv = (const float*)d_in[5];
    const float* bv = (const float*)d_in[6];
    const float* Wo = (const float*)d_in[7];
    const float* bo = (const float*)d_in[8];

    float* out = (float*)d_out;                        // [32,512,256]
    float* avg = out + (size_t)NROWS * DD;             // [32,512,512]

    float* tmp = nullptr;
    cudaGetSymbolAddress((void**)&tmp, g_tmp);

    cudaFuncSetAttribute(mma_qkv, cudaFuncAttributeMaxDynamicSharedMemorySize, TN_SMEM_B);
    cudaFuncSetAttribute(mma_out, cudaFuncAttributeMaxDynamicSharedMemorySize, TN_SMEM_B);
    cudaFuncSetAttribute(mma_nn,  cudaFuncAttributeMaxDynamicSharedMemorySize, NN_SMEM_B);
    cudaFuncSetAttribute(attn_sparsemax_kernel,
                         cudaFuncAttributeMaxDynamicSharedMemorySize, ATTN_SMEM_BYTES);

    // 1) QKV projections: q,k -> bf16 hi/lo (pre-split); v -> fp32 g_v
    {
        dim3 grid(6, 128);
        mma_qkv<<<grid, 256, TN_SMEM_B>>>(x, Wq, bq, Wk, bk, Wv, bv);
    }

    // 2) scores (HMMA) + sparsemax + head average -> avg_attention (in d_out)
    attn_sparsemax_kernel<<<NROWS / 32, 512, ATTN_SMEM_BYTES>>>(avg);

    // 3) tmp[b] = avg[b] @ v[b]
    {
        dim3 grid(2, 4, BB);
        mma_nn<<<grid, 256, NN_SMEM_B>>>(avg, tmp);
    }

    // 4) out = tmp @ Wo^T + bo
    {
        dim3 grid(2, 128);
        mma_out<<<grid, 256, TN_SMEM_B>>>(Wo, bo, out);
    }
}

// round 16
// speedup vs baseline: 1.7131x; 1.0807x over previous
#include <cuda_runtime.h>
#include <cuda_bf16.h>
#include <cstdint>
#include <math.h>
#include <math_constants.h>

// Problem constants
#define BB 32
#define SS 512
#define DD 256
#define HH 8
#define DHH 32
#define NROWS (BB*SS)

// Scratch (__device__ globals; allocation is banned)
__device__ uint16_t g_qkh[(size_t)NROWS * 512];   // bf16 hi: [row][0:256)=q, [256:512)=k
__device__ uint16_t g_qkl[(size_t)NROWS * 512];   // bf16 lo
__device__ float    g_v[(size_t)NROWS * 256];     // v fp32  [b*512+t][e]
__device__ float    g_tmp[(size_t)NROWS * 256];   // avg @ v result

// ---------------------------------------------------------------------------
// bf16 split + pack helpers (3xBF16 fp32 emulation)
// ---------------------------------------------------------------------------
__device__ __forceinline__ void splitpk(float x, float y, uint32_t& h, uint32_t& l) {
    __nv_bfloat16 hx = __float2bfloat16(x), hy = __float2bfloat16(y);
    float rx = x - __bfloat162float(hx);
    float ry = y - __bfloat162float(hy);
    __nv_bfloat16 lx = __float2bfloat16(rx), ly = __float2bfloat16(ry);
    h = (uint32_t)__bfloat16_as_ushort(hx) | ((uint32_t)__bfloat16_as_ushort(hy) << 16);
    l = (uint32_t)__bfloat16_as_ushort(lx) | ((uint32_t)__bfloat16_as_ushort(ly) << 16);
}

__device__ __forceinline__ uint32_t cvta_s(const void* p) {
    return (uint32_t)__cvta_generic_to_shared(p);
}

__device__ __forceinline__ void ldmx4(uint32_t r[4], uint32_t addr) {
    asm volatile("ldmatrix.sync.aligned.m8n8.x4.shared.b16 {%0,%1,%2,%3}, [%4];"
                 : "=r"(r[0]), "=r"(r[1]), "=r"(r[2]), "=r"(r[3]) : "r"(addr));
}
__device__ __forceinline__ void ldmx2(uint32_t r[2], uint32_t addr) {
    asm volatile("ldmatrix.sync.aligned.m8n8.x2.shared.b16 {%0,%1}, [%2];"
                 : "=r"(r[0]), "=r"(r[1]) : "r"(addr));
}
__device__ __forceinline__ void ldmx4t(uint32_t r[4], uint32_t addr) {
    asm volatile("ldmatrix.sync.aligned.m8n8.x4.trans.shared.b16 {%0,%1,%2,%3}, [%4];"
                 : "=r"(r[0]), "=r"(r[1]), "=r"(r[2]), "=r"(r[3]) : "r"(addr));
}

__device__ __forceinline__ void mma16816(float c[4], const uint32_t a[4],
                                         uint32_t b0, uint32_t b1) {
    asm volatile(
        "mma.sync.aligned.m16n8k16.row.col.f32.bf16.bf16.f32 "
        "{%0,%1,%2,%3}, {%4,%5,%6,%7}, {%8,%9}, {%0,%1,%2,%3};"
        : "+f"(c[0]), "+f"(c[1]), "+f"(c[2]), "+f"(c[3])
        : "r"(a[0]), "r"(a[1]), "r"(a[2]), "r"(a[3]), "r"(b0), "r"(b1));
}

// cp.async 16B + group controls
__device__ __forceinline__ void cpa16(uint32_t dst_smem, const void* src) {
    asm volatile("cp.async.cg.shared.global [%0], [%1], 16;"
                 :: "r"(dst_smem), "l"(src));
}
#define CPA_COMMIT() asm volatile("cp.async.commit_group;" ::: "memory")
#define CPA_WAIT0()  asm volatile("cp.async.wait_group 0;" ::: "memory")

// ---------------------------------------------------------------------------
// Tile strides
// ---------------------------------------------------------------------------
#define AT_STR 40    // K-major tiles: 32 k + 8 pad
#define BN_STR 136   // NN B tile [k][n]: 128 n + 8 pad

#define TN_TILE_B  (128 * AT_STR * 2)            // 10240
#define TN_BUF_B   (4 * TN_TILE_B)               // 40960
#define TN_SMEM_B  (2 * TN_BUF_B)                // 81920

#define NN_BT_B    (32 * BN_STR * 2)             // 8704
#define NN_BUF_B   (2 * TN_TILE_B + 2 * NN_BT_B) // 37888
#define NN_SMEM_B  (2 * NN_BUF_B)                // 75776

// Stage a 128x32 fp32 K-contig tile -> hi/lo bf16 smem (row stride AT_STR)
__device__ __forceinline__ void stage_tn(uint16_t* hi, uint16_t* lo,
                                         const float4 f[4], int tid) {
    int row = tid >> 1, kh = (tid & 1) * 16;
    uint4 H0, H1, L0, L1;
    splitpk(f[0].x, f[0].y, H0.x, L0.x); splitpk(f[0].z, f[0].w, H0.y, L0.y);
    splitpk(f[1].x, f[1].y, H0.z, L0.z); splitpk(f[1].z, f[1].w, H0.w, L0.w);
    splitpk(f[2].x, f[2].y, H1.x, L1.x); splitpk(f[2].z, f[2].w, H1.y, L1.y);
    splitpk(f[3].x, f[3].y, H1.z, L1.z); splitpk(f[3].z, f[3].w, H1.w, L1.w);
    *(uint4*)(hi + row * AT_STR + kh)     = H0;
    *(uint4*)(hi + row * AT_STR + kh + 8) = H1;
    *(uint4*)(lo + row * AT_STR + kh)     = L0;
    *(uint4*)(lo + row * AT_STR + kh + 8) = L1;
}

// Stage a 32x128 fp32 N-contig tile -> hi/lo bf16 smem [k][n] (stride BN_STR)
__device__ __forceinline__ void stage_nn_b(uint16_t* hi, uint16_t* lo,
                                           const float4 f[4], int tid) {
    int k = tid >> 3, nq = (tid & 7) * 16;
    uint4 H0, H1, L0, L1;
    splitpk(f[0].x, f[0].y, H0.x, L0.x); splitpk(f[0].z, f[0].w, H0.y, L0.y);
    splitpk(f[1].x, f[1].y, H0.z, L0.z); splitpk(f[1].z, f[1].w, H0.w, L0.w);
    splitpk(f[2].x, f[2].y, H1.x, L1.x); splitpk(f[2].z, f[2].w, H1.y, L1.y);
    splitpk(f[3].x, f[3].y, H1.z, L1.z); splitpk(f[3].z, f[3].w, H1.w, L1.w);
    *(uint4*)(hi + k * BN_STR + nq)     = H0;
    *(uint4*)(hi + k * BN_STR + nq + 8) = H1;
    *(uint4*)(lo + k * BN_STR + nq)     = L0;
    *(uint4*)(lo + k * BN_STR + nq + 8) = L1;
}

// Warp-level K-chunk compute: 64x32 warp tile, 3-pass split (pass-outermost).
template<bool TRANSB>
__device__ __forceinline__ void compute_chunk(
    float c[4][4][4],
    const uint16_t* sAhi, const uint16_t* sAlo,
    const uint16_t* sBhi, const uint16_t* sBlo,
    int lane, int mrow0, int ncol0)
{
    const int lr = lane & 7, lg = lane >> 3;
#pragma unroll
    for (int k16 = 0; k16 < 32; k16 += 16) {
        uint32_t ah[4][4], al[4][4];
        uint32_t aoff = (uint32_t)(((mrow0 + (lane & 15)) * AT_STR + k16 + ((lane >> 4) << 3)) * 2);
#pragma unroll
        for (int mi = 0; mi < 4; ++mi) {
            ldmx4(ah[mi], cvta_s(sAhi) + aoff + mi * (16 * AT_STR * 2));
            ldmx4(al[mi], cvta_s(sAlo) + aoff + mi * (16 * AT_STR * 2));
        }
        uint32_t bh[2][4], bl[2][4];
#pragma unroll
        for (int nb = 0; nb < 2; ++nb) {
            uint32_t boff;
            if (TRANSB) {
                boff = (uint32_t)(((k16 + lr + ((lg & 1) << 3)) * BN_STR
                                   + ncol0 + nb * 16 + ((lg & 2) << 2)) * 2);
                ldmx4t(bh[nb], cvta_s(sBhi) + boff);
                ldmx4t(bl[nb], cvta_s(sBlo) + boff);
            } else {
                boff = (uint32_t)(((ncol0 + nb * 16 + lr + ((lg & 2) << 2)) * AT_STR
                                   + k16 + ((lg & 1) << 3)) * 2);
                ldmx4(bh[nb], cvta_s(sBhi) + boff);
                ldmx4(bl[nb], cvta_s(sBlo) + boff);
            }
        }
#pragma unroll
        for (int pass = 0; pass < 3; ++pass)
#pragma unroll
            for (int mi = 0; mi < 4; ++mi)
#pragma unroll
                for (int nb = 0; nb < 2; ++nb)
#pragma unroll
                    for (int half = 0; half < 2; ++half) {
                        float* cc = c[mi][nb * 2 + half];
                        const uint32_t* aa = (pass == 2) ? al[mi] : ah[mi];
                        uint32_t b0 = (pass == 1) ? bl[nb][half * 2]     : bh[nb][half * 2];
                        uint32_t b1 = (pass == 1) ? bl[nb][half * 2 + 1] : bh[nb][half * 2 + 1];
                        mma16816(cc, aa, b0, b1);
                    }
    }
}

__device__ __forceinline__ void epilogue_store(
    float c[4][4][4], float* __restrict__ C, const float* __restrict__ bias,
    int ldc, int m0, int cn0, int mrow0, int ncol0, int lane)
{
#pragma unroll
    for (int mi = 0; mi < 4; ++mi) {
        int r = m0 + mrow0 + mi * 16 + (lane >> 2);
#pragma unroll
        for (int ni = 0; ni < 4; ++ni) {
            int cl = ncol0 + ni * 8 + ((lane & 3) << 1);
            float b0 = 0.f, b1 = 0.f;
            if (bias) { b0 = bias[cl]; b1 = bias[cl + 1]; }
            float2 v0 = make_float2(c[mi][ni][0] + b0, c[mi][ni][1] + b1);
            float2 v1 = make_float2(c[mi][ni][2] + b0, c[mi][ni][3] + b1);
            *(float2*)(C + (size_t)r * ldc + cn0 + cl) = v0;
            *(float2*)(C + (size_t)(r + 8) * ldc + cn0 + cl) = v1;
        }
    }
}

// Split epilogue: write q/k as bf16 hi/lo into g_qkh/g_qkl (row len 512)
__device__ __forceinline__ void epilogue_split(
    float c[4][4][4], const float* __restrict__ bias,
    int m0, int zbase, int mrow0, int ncol0, int lane)
{
#pragma unroll
    for (int mi = 0; mi < 4; ++mi) {
        int r = m0 + mrow0 + mi * 16 + (lane >> 2);
#pragma unroll
        for (int ni = 0; ni < 4; ++ni) {
            int cl = ncol0 + ni * 8 + ((lane & 3) << 1);
            float b0 = bias[cl], b1 = bias[cl + 1];
            uint32_t h0, l0, h1, l1;
            splitpk(c[mi][ni][0] + b0, c[mi][ni][1] + b1, h0, l0);
            splitpk(c[mi][ni][2] + b0, c[mi][ni][3] + b1, h1, l1);
            size_t o0 = (size_t)r * 512 + zbase + cl;
            size_t o1 = (size_t)(r + 8) * 512 + zbase + cl;
            *(uint32_t*)(g_qkh + o0) = h0;
            *(uint32_t*)(g_qkl + o0) = l0;
            *(uint32_t*)(g_qkh + o1) = h1;
            *(uint32_t*)(g_qkl + o1) = l1;
        }
    }
}

// ---------------------------------------------------------------------------
// TN GEMM body — 256 threads, 8 warps (2x4), double-buffered.
// ---------------------------------------------------------------------------
__device__ __forceinline__ void gemm_tn_mma_body(
    char* sm, float c[4][4][4],
    const float* __restrict__ A, const float* __restrict__ B,
    int K, int lda, int ldb, int m0, int lane, int mrow0, int ncol0)
{
    const int tid = threadIdx.x;
    const int row = tid >> 1, kh = (tid & 1) * 16;

    const float* pA = A + (size_t)(m0 + row) * lda + kh;
    const float* pB = B + (size_t)row * ldb + kh;

    float4 fa[4], fb[4];
#pragma unroll
    for (int i = 0; i < 4; ++i) {
        fa[i] = *(const float4*)(pA + i * 4);
        fb[i] = *(const float4*)(pB + i * 4);
    }
    {
        uint16_t* b0 = (uint16_t*)sm;
        stage_tn(b0,             b0 + TN_TILE_B / 2,     fa, tid);
        stage_tn(b0 + TN_TILE_B, b0 + 3 * TN_TILE_B / 2, fb, tid);
    }
    __syncthreads();

    int ib = 0;
    for (int k0 = 0; k0 < K; k0 += 32, ib ^= 1) {
        const bool has_next = (k0 + 32 < K);
        if (has_next) {
#pragma unroll
            for (int i = 0; i < 4; ++i) {
                fa[i] = *(const float4*)(pA + k0 + 32 + i * 4);
                fb[i] = *(const float4*)(pB + k0 + 32 + i * 4);
            }
        }
        uint16_t* cur = (uint16_t*)(sm + ib * TN_BUF_B);
        compute_chunk<false>(c, cur, cur + TN_TILE_B / 2,
                             cur + TN_TILE_B, cur + 3 * TN_TILE_B / 2,
                             lane, mrow0, ncol0);
        if (has_next) {
            uint16_t* nxt = (uint16_t*)(sm + (ib ^ 1) * TN_BUF_B);
            stage_tn(nxt,             nxt + TN_TILE_B / 2,     fa, tid);
            stage_tn(nxt + TN_TILE_B, nxt + 3 * TN_TILE_B / 2, fb, tid);
        }
        __syncthreads();
    }
}

__global__ __launch_bounds__(256) void mma_qkv(
    const float* __restrict__ x,
    const float* __restrict__ Wq, const float* __restrict__ bq,
    const float* __restrict__ Wk, const float* __restrict__ bk,
    const float* __restrict__ Wv, const float* __restrict__ bv)
{
    extern __shared__ __align__(16) char sm[];
    const int tid = threadIdx.x, lane = tid & 31, warp = tid >> 5;
    const int mrow0 = (warp & 1) * 64, ncol0 = (warp >> 1) * 32;
    const int z = blockIdx.x;
    const int m0 = blockIdx.y * 128;
    const float* B; const float* bias;
    if (z < 2)      { B = Wq + (size_t)z * 128 * 256;       bias = bq + z * 128; }
    else if (z < 4) { B = Wk + (size_t)(z - 2) * 128 * 256; bias = bk + (z - 2) * 128; }
    else            { B = Wv + (size_t)(z - 4) * 128 * 256; bias = bv + (z - 4) * 128; }

    float c[4][4][4];
#pragma unroll
    for (int i = 0; i < 4; ++i)
#pragma unroll
        for (int j = 0; j < 4; ++j)
#pragma unroll
            for (int q = 0; q < 4; ++q) c[i][j][q] = 0.f;

    gemm_tn_mma_body(sm, c, x, B, 256, 256, 256, m0, lane, mrow0, ncol0);

    if (z < 4) epilogue_split(c, bias, m0, z * 128, mrow0, ncol0, lane);
    else       epilogue_store(c, g_v, bias, 256, m0, (z - 4) * 128, mrow0, ncol0, lane);
}

__global__ __launch_bounds__(256) void mma_out(
    const float* __restrict__ Wo, const float* __restrict__ bo,
    float* __restrict__ out)
{
    extern __shared__ __align__(16) char sm[];
    const int tid = threadIdx.x, lane = tid & 31, warp = tid >> 5;
    const int mrow0 = (warp & 1) * 64, ncol0 = (warp >> 1) * 32;
    const int n0 = blockIdx.x * 128;
    const int m0 = blockIdx.y * 128;

    float c[4][4][4];
#pragma unroll
    for (int i = 0; i < 4; ++i)
#pragma unroll
        for (int j = 0; j < 4; ++j)
#pragma unroll
            for (int q = 0; q < 4; ++q) c[i][j][q] = 0.f;

    gemm_tn_mma_body(sm, c, g_tmp, Wo + (size_t)n0 * 256, 256, 256, 256, m0,
                     lane, mrow0, ncol0);
    epilogue_store(c, out, bo + n0, 256, m0, n0, mrow0, ncol0, lane);
}

// ---------------------------------------------------------------------------
// NN batched (double-buffered): tmp[b] = avg[b] @ v[b]   (v from g_v, ldb=256)
// ---------------------------------------------------------------------------
__global__ __launch_bounds__(256) void mma_nn(
    const float* __restrict__ avg, float* __restrict__ tmp)
{
    extern __shared__ __align__(16) char sm[];
    const int tid = threadIdx.x;
    const int lane = tid & 31, warp = tid >> 5;
    const int mrow0 = (warp & 1) * 64, ncol0 = (warp >> 1) * 32;
    const int n0 = blockIdx.x * 128;
    const int m0 = blockIdx.y * 128;
    const int b  = blockIdx.z;

    const float* A = avg + (size_t)b * 512 * 512;
    const float* B = g_v + (size_t)b * 512 * 256;

    float c[4][4][4];
#pragma unroll
    for (int i = 0; i < 4; ++i)
#pragma unroll
        for (int j = 0; j < 4; ++j)
#pragma unroll
            for (int q = 0; q < 4; ++q) c[i][j][q] = 0.f;

    const int row = tid >> 1, kh = (tid & 1) * 16;
    const int bk = tid >> 3, bn = (tid & 7) * 16;
    const float* pA = A + (size_t)(m0 + row) * 512 + kh;
    const float* pB = B + n0 + bn;

    float4 fa[4], fb[4];
#pragma unroll
    for (int i = 0; i < 4; ++i) {
        fa[i] = *(const float4*)(pA + i * 4);
        fb[i] = *(const float4*)(pB + (size_t)bk * 256 + i * 4);
    }
    {
        uint16_t* a0 = (uint16_t*)sm;
        uint16_t* b0 = (uint16_t*)(sm + 2 * TN_TILE_B);
        stage_tn(a0, a0 + TN_TILE_B / 2, fa, tid);
        stage_nn_b(b0, b0 + NN_BT_B / 2, fb, tid);
    }
    __syncthreads();

    int ib = 0;
    for (int k0 = 0; k0 < 512; k0 += 32, ib ^= 1) {
        const bool has_next = (k0 + 32 < 512);
        if (has_next) {
#pragma unroll
            for (int i = 0; i < 4; ++i) {
                fa[i] = *(const float4*)(pA + k0 + 32 + i * 4);
                fb[i] = *(const float4*)(pB + (size_t)(k0 + 32 + bk) * 256 + i * 4);
            }
        }
        uint16_t* ca = (uint16_t*)(sm + ib * NN_BUF_B);
        uint16_t* cb = (uint16_t*)(sm + ib * NN_BUF_B + 2 * TN_TILE_B);
        compute_chunk<true>(c, ca, ca + TN_TILE_B / 2, cb, cb + NN_BT_B / 2,
                            lane, mrow0, ncol0);
        if (has_next) {
            uint16_t* na = (uint16_t*)(sm + (ib ^ 1) * NN_BUF_B);
            uint16_t* nb = (uint16_t*)(sm + (ib ^ 1) * NN_BUF_B + 2 * TN_TILE_B);
            stage_tn(na, na + TN_TILE_B / 2, fa, tid);
            stage_nn_b(nb, nb + NN_BT_B / 2, fb, tid);
        }
        __syncthreads();
    }
    epilogue_store(c, tmp, nullptr, 256, b * 512 + m0, n0, mrow0, ncol0, lane);
}

// ---------------------------------------------------------------------------
// Attention v5: cp.async software pipeline.
// 128-key sub-chunks, 2-slot ring; next sub-chunk copy issued before MMA of
// the current one; next head's Q + K(0) issued before sparsemax. Scores via
// 3xBF16 HMMA (8 keys/warp, ldmatrix.x2 B-frags), exact dual-query Michelot
// sparsemax with zmax-1 tau init.
// Smem: Kring 2x(hi10240+lo10240)=40960, Q hi/lo 2x2560, Ssc 32x522x4=66816
//       -> 112896 B (2 blocks/SM).
// ---------------------------------------------------------------------------
#define SC_STR 522
#define AQ_H  40960
#define AQ_L  43520
#define ASC   46080
#define ATTN_SMEM_BYTES (46080 + 32 * SC_STR * 4)   // 112896

__global__ __launch_bounds__(512, 2) void attn_sparsemax_kernel(float* __restrict__ avg)
{
    extern __shared__ __align__(16) char sm[];
    float* Ssc = (float*)(sm + ASC);

    const int tid  = threadIdx.x;
    const int lane = tid & 31, w = tid >> 5;
    const int b    = blockIdx.x >> 4;
    const int s0   = (blockIdx.x & 15) << 5;

    const uint16_t* qkh = g_qkh + (size_t)b * 512 * 512;
    const uint16_t* qkl = g_qkl + (size_t)b * 512 * 512;

    float acc[2][16];
#pragma unroll
    for (int qi = 0; qi < 2; ++qi)
#pragma unroll
        for (int i = 0; i < 16; ++i) acc[qi][i] = 0.f;

    // ---- cp.async stage issuers (no waits; caller commits) ----
    // K sub-chunk: 128 keys x 32e hi+lo. Thread t copies hi unit t, lo unit t.
    auto issue_K = [&](int h, int ck, int ring) {
        int rrow = tid >> 2, seg = (tid & 3) * 8;
        int key = ck * 128 + rrow;
        size_t gofs = (size_t)key * 512 + 256 + h * 32 + seg;
        uint32_t dhi = cvta_s(sm) + (uint32_t)(ring * 20480 + (rrow * AT_STR + seg) * 2);
        cpa16(dhi,         qkh + gofs);
        cpa16(dhi + 10240, qkl + gofs);
    };
    // Q: 32 rows x 32e hi+lo = 256 16B units; threads 0..255 take one.
    auto issue_Q = [&](int h) {
        if (tid < 256) {
            int u = tid & 127;
            int rrow = u >> 2, seg = (u & 3) * 8;
            const uint16_t* src = (tid < 128) ? qkh : qkl;
            uint32_t dst = cvta_s(sm) + (uint32_t)((tid < 128 ? AQ_H : AQ_L)
                                                   + (rrow * AT_STR + seg) * 2);
            cpa16(dst, src + (size_t)(s0 + rrow) * 512 + h * 32 + seg);
        }
    };

    // prologue: head 0, sub-chunk 0 + Q(0)
    issue_Q(0);
    issue_K(0, 0, 0);
    CPA_COMMIT();

    for (int h = 0; h < HH; ++h) {
#pragma unroll
        for (int ck = 0; ck < 4; ++ck) {
            const int stage = h * 4 + ck;
            const int ring = stage & 1;
            CPA_WAIT0();          // current stage's copies complete (thread-local)
            __syncthreads();      // ...and visible block-wide; also retires MMA(stage-1)
            // issue next K sub-chunk within this head (ring slot (stage+1)&1 is
            // free: its MMA finished before the sync above)
            if (ck < 3) {
                issue_K(h, ck + 1, (stage + 1) & 1);
                CPA_COMMIT();
            }

            // ---- score MMA: warp w -> 8 keys [ck*128 + w*8, +8) ----
            const uint32_t kh_base = cvta_s(sm) + (uint32_t)(ring * 20480);
            const uint32_t kl_base = kh_base + 10240;
            const uint32_t qh_base = cvta_s(sm) + AQ_H;
            const uint32_t ql_base = cvta_s(sm) + AQ_L;

            float sc[2][4];
#pragma unroll
            for (int mi = 0; mi < 2; ++mi)
#pragma unroll
                for (int q = 0; q < 4; ++q) sc[mi][q] = 0.f;

#pragma unroll
            for (int k16 = 0; k16 < 32; k16 += 16) {
                uint32_t aoff = (uint32_t)(((lane & 15) * AT_STR + k16 + ((lane >> 4) << 3)) * 2);
                uint32_t ah0[4], ah1[4], al0[4], al1[4];
                ldmx4(ah0, qh_base + aoff);
                ldmx4(ah1, qh_base + aoff + 16 * AT_STR * 2);
                ldmx4(al0, ql_base + aoff);
                ldmx4(al1, ql_base + aoff + 16 * AT_STR * 2);

                int l16 = lane & 15;
                uint32_t boff = (uint32_t)(((w * 8 + (l16 & 7)) * AT_STR
                                            + k16 + ((l16 >> 3) << 3)) * 2);
                uint32_t bh[2], bl[2];
                ldmx2(bh, kh_base + boff);
                ldmx2(bl, kl_base + boff);

                mma16816(sc[0], ah0, bh[0], bh[1]);
                mma16816(sc[1], ah1, bh[0], bh[1]);
                mma16816(sc[0], ah0, bl[0], bl[1]);
                mma16816(sc[1], ah1, bl[0], bl[1]);
                mma16816(sc[0], al0, bh[0], bh[1]);
                mma16816(sc[1], al1, bh[0], bh[1]);
            }

            // scale + diagonal mask + store
#pragma unroll
            for (int mi = 0; mi < 2; ++mi) {
                int gc = ck * 128 + w * 8 + ((lane & 3) << 1);
                int r0 = mi * 16 + (lane >> 2);
                int r1 = r0 + 8;
                float v0 = sc[mi][0] * 0.17677669529663687f;
                float v1 = sc[mi][1] * 0.17677669529663687f;
                float v2 = sc[mi][2] * 0.17677669529663687f;
                float v3 = sc[mi][3] * 0.17677669529663687f;
                if (gc     == s0 + r0) v0 = -CUDART_INF_F;
                if (gc + 1 == s0 + r0) v1 = -CUDART_INF_F;
                if (gc     == s0 + r1) v2 = -CUDART_INF_F;
                if (gc + 1 == s0 + r1) v3 = -CUDART_INF_F;
                *(float2*)&Ssc[r0 * SC_STR + gc] = make_float2(v0, v1);
                *(float2*)&Ssc[r1 * SC_STR + gc] = make_float2(v2, v3);
            }
        }

        __syncthreads();   // Ssc complete; all Q reads done
        // issue next head's Q + K(0) so the copy runs under sparsemax
        if (h < HH - 1) {
            issue_Q(h + 1);
            issue_K(h + 1, 0, (h * 4 + 4) & 1);
            CPA_COMMIT();
        }

        // ---- dual-query exact sparsemax (Michelot), tau0 = zmax - 1 ----
        float zz0[16], zz1[16];
        {
            int q0 = w * 2, q1 = w * 2 + 1;
#pragma unroll
            for (int i = 0; i < 16; ++i) {
                zz0[i] = Ssc[q0 * SC_STR + lane + 32 * i];
                zz1[i] = Ssc[q1 * SC_STR + lane + 32 * i];
            }
        }
        float m0v = -CUDART_INF_F, m1v = -CUDART_INF_F;
#pragma unroll
        for (int i = 0; i < 16; ++i) {
            m0v = fmaxf(m0v, zz0[i]);
            m1v = fmaxf(m1v, zz1[i]);
        }
#pragma unroll
        for (int o = 16; o; o >>= 1) {
            m0v = fmaxf(m0v, __shfl_xor_sync(0xffffffffu, m0v, o));
            m1v = fmaxf(m1v, __shfl_xor_sync(0xffffffffu, m1v, o));
        }
        float tau0 = m0v - 1.0f, tau1 = m1v - 1.0f;
        int prev0 = -1, prev1 = -1;
        bool done0 = false, done1 = false;
        for (int it = 0; it < 64; ++it) {
            float sa0 = 0.f, sa1 = 0.f;
            int ca0 = 0, ca1 = 0;
#pragma unroll
            for (int i = 0; i < 16; ++i) {
                if (zz0[i] > tau0) { sa0 += zz0[i]; ca0++; }
                if (zz1[i] > tau1) { sa1 += zz1[i]; ca1++; }
            }
#pragma unroll
            for (int o = 16; o; o >>= 1) {
                sa0 += __shfl_xor_sync(0xffffffffu, sa0, o);
                sa1 += __shfl_xor_sync(0xffffffffu, sa1, o);
            }
            ca0 = __reduce_add_sync(0xffffffffu, ca0);
            ca1 = __reduce_add_sync(0xffffffffu, ca1);
            if (!done0) {
                if (ca0 == prev0 || ca0 == 0) done0 = true;
                else { prev0 = ca0; tau0 = (sa0 - 1.0f) / (float)ca0; }
            }
            if (!done1) {
                if (ca1 == prev1 || ca1 == 0) done1 = true;
                else { prev1 = ca1; tau1 = (sa1 - 1.0f) / (float)ca1; }
            }
            if (done0 && done1) break;
        }
#pragma unroll
        for (int i = 0; i < 16; ++i) {
            acc[0][i] += fmaxf(zz0[i] - tau0, 0.f) * 0.125f;
            acc[1][i] += fmaxf(zz1[i] - tau1, 0.f) * 0.125f;
        }
    }

#pragma unroll
    for (int qi = 0; qi < 2; ++qi) {
        float* dst = avg + (size_t)(b * 512 + s0 + w * 2 + qi) * 512;
#pragma unroll
        for (int i = 0; i < 16; ++i) dst[lane + 32 * i] = acc[qi][i];
    }
}

// ---------------------------------------------------------------------------
extern "C" void kernel_launch(void* const* d_in, const int* in_sizes, int n_in,
                              void* d_out, int out_size)
{
    const float* x  = (const float*)d_in[0];
    const float* Wq = (const float*)d_in[1];
    const float* bq = (const float*)d_in[2];
    const float* Wk = (const float*)d_in[3];
    const float* bk = (const float*)d_in[4];
    const float* Wv = (const float*)d_in[5];
    const float* bv = (const float*)d_in[6];
    const float* Wo = (const float*)d_in[7];
    const float* bo = (const float*)d_in[8];

    float* out = (float*)d_out;                        // [32,512,256]
    float* avg = out + (size_t)NROWS * DD;             // [32,512,512]

    float* tmp = nullptr;
    cudaGetSymbolAddress((void**)&tmp, g_tmp);

    cudaFuncSetAttribute(mma_qkv, cudaFuncAttributeMaxDynamicSharedMemorySize, TN_SMEM_B);
    cudaFuncSetAttribute(mma_out, cudaFuncAttributeMaxDynamicSharedMemorySize, TN_SMEM_B);
    cudaFuncSetAttribute(mma_nn,  cudaFuncAttributeMaxDynamicSharedMemorySize, NN_SMEM_B);
    cudaFuncSetAttribute(attn_sparsemax_kernel,
                         cudaFuncAttributeMaxDynamicSharedMemorySize, ATTN_SMEM_BYTES);

    // 1) QKV projections: q,k -> bf16 hi/lo (pre-split); v -> fp32 g_v
    {
        dim3 grid(6, 128);
        mma_qkv<<<grid, 256, TN_SMEM_B>>>(x, Wq, bq, Wk, bk, Wv, bv);
    }

    // 2) scores (HMMA, cp.async pipelined) + sparsemax + head avg -> d_out
    attn_sparsemax_kernel<<<NROWS / 32, 512, ATTN_SMEM_BYTES>>>(avg);

    // 3) tmp[b] = avg[b] @ v[b]
    {
        dim3 grid(2, 4, BB);
        mma_nn<<<grid, 256, NN_SMEM_B>>>(avg, tmp);
    }

    // 4) out = tmp @ Wo^T + bo
    {
        dim3 grid(2, 128);
        mma_out<<<grid, 256, TN_SMEM_B>>>(Wo, bo, out);
    }
}

// round 17
// speedup vs baseline: 1.8437x; 1.0762x over previous
#include <cuda_runtime.h>
#include <cuda_bf16.h>
#include <cstdint>
#include <math.h>
#include <math_constants.h>

// Problem constants
#define BB 32
#define SS 512
#define DD 256
#define HH 8
#define DHH 32
#define NROWS (BB*SS)

// ---------------------------------------------------------------------------
// Scratch (__device__ globals; allocation is banned) — all operands pre-split
// ---------------------------------------------------------------------------
__device__ uint16_t g_qkh[(size_t)NROWS * 512];       // q|k bf16 hi  [row][0:256)=q,[256:512)=k
__device__ uint16_t g_qkl[(size_t)NROWS * 512];       // q|k bf16 lo
__device__ uint16_t g_xh [(size_t)NROWS * 256];       // x split
__device__ uint16_t g_xl [(size_t)NROWS * 256];
__device__ uint16_t g_wh [(size_t)8 * 128 * 256];     // [Wq|Wk|Wv|Wo] as 8 slabs of 128x256
__device__ uint16_t g_wl [(size_t)8 * 128 * 256];
__device__ uint16_t g_vh [(size_t)NROWS * 256];       // v split
__device__ uint16_t g_vl [(size_t)NROWS * 256];
__device__ uint16_t g_avgh[(size_t)BB * 512 * 512];   // avg split (fp32 copy goes to d_out)
__device__ uint16_t g_avgl[(size_t)BB * 512 * 512];
__device__ uint16_t g_tmph[(size_t)NROWS * 256];      // avg@v split
__device__ uint16_t g_tmpl[(size_t)NROWS * 256];

// ---------------------------------------------------------------------------
// Helpers
// ---------------------------------------------------------------------------
__device__ __forceinline__ void splitpk(float x, float y, uint32_t& h, uint32_t& l) {
    __nv_bfloat16 hx = __float2bfloat16(x), hy = __float2bfloat16(y);
    float rx = x - __bfloat162float(hx);
    float ry = y - __bfloat162float(hy);
    __nv_bfloat16 lx = __float2bfloat16(rx), ly = __float2bfloat16(ry);
    h = (uint32_t)__bfloat16_as_ushort(hx) | ((uint32_t)__bfloat16_as_ushort(hy) << 16);
    l = (uint32_t)__bfloat16_as_ushort(lx) | ((uint32_t)__bfloat16_as_ushort(ly) << 16);
}
__device__ __forceinline__ void split1(float x, uint16_t& h, uint16_t& l) {
    __nv_bfloat16 hx = __float2bfloat16(x);
    __nv_bfloat16 lx = __float2bfloat16(x - __bfloat162float(hx));
    h = __bfloat16_as_ushort(hx);
    l = __bfloat16_as_ushort(lx);
}

__device__ __forceinline__ uint32_t cvta_s(const void* p) {
    return (uint32_t)__cvta_generic_to_shared(p);
}
__device__ __forceinline__ void ldmx4(uint32_t r[4], uint32_t addr) {
    asm volatile("ldmatrix.sync.aligned.m8n8.x4.shared.b16 {%0,%1,%2,%3}, [%4];"
                 : "=r"(r[0]), "=r"(r[1]), "=r"(r[2]), "=r"(r[3]) : "r"(addr));
}
__device__ __forceinline__ void ldmx2(uint32_t r[2], uint32_t addr) {
    asm volatile("ldmatrix.sync.aligned.m8n8.x2.shared.b16 {%0,%1}, [%2];"
                 : "=r"(r[0]), "=r"(r[1]) : "r"(addr));
}
__device__ __forceinline__ void ldmx4t(uint32_t r[4], uint32_t addr) {
    asm volatile("ldmatrix.sync.aligned.m8n8.x4.trans.shared.b16 {%0,%1,%2,%3}, [%4];"
                 : "=r"(r[0]), "=r"(r[1]), "=r"(r[2]), "=r"(r[3]) : "r"(addr));
}
__device__ __forceinline__ void mma16816(float c[4], const uint32_t a[4],
                                         uint32_t b0, uint32_t b1) {
    asm volatile(
        "mma.sync.aligned.m16n8k16.row.col.f32.bf16.bf16.f32 "
        "{%0,%1,%2,%3}, {%4,%5,%6,%7}, {%8,%9}, {%0,%1,%2,%3};"
        : "+f"(c[0]), "+f"(c[1]), "+f"(c[2]), "+f"(c[3])
        : "r"(a[0]), "r"(a[1]), "r"(a[2]), "r"(a[3]), "r"(b0), "r"(b1));
}
__device__ __forceinline__ void cpa16(uint32_t dst_smem, const void* src) {
    asm volatile("cp.async.cg.shared.global [%0], [%1], 16;"
                 :: "r"(dst_smem), "l"(src));
}
#define CPA_COMMIT() asm volatile("cp.async.commit_group;" ::: "memory")
#define CPA_WAIT0()  asm volatile("cp.async.wait_group 0;" ::: "memory")

// ---------------------------------------------------------------------------
// Tile strides / smem layouts
// ---------------------------------------------------------------------------
#define AT_STR 40    // K-major tiles: 32 k + 8 pad (bf16 elems)
#define BN_STR 136   // NN B tile [k][n]: 128 n + 8 pad

#define TN_TILE_B  (128 * AT_STR * 2)            // 10240
#define TN_BUF_B   (4 * TN_TILE_B)               // Ahi,Alo,Bhi,Blo = 40960
#define TN_SMEM_B  (2 * TN_BUF_B)                // 81920

#define NN_BT_B    (32 * BN_STR * 2)             // 8704
#define NN_BUF_B   (2 * TN_TILE_B + 2 * NN_BT_B) // 37888
#define NN_SMEM_B  (2 * NN_BUF_B)                // 75776

// ---------------------------------------------------------------------------
// split_inputs: x and [Wq|Wk|Wv|Wo] -> bf16 hi/lo
// ---------------------------------------------------------------------------
#define NX4 ((size_t)NROWS * 256 / 4)     // 1,048,576 float4 of x
#define NW4 ((size_t)65536 / 4)           // 16,384 float4 per weight matrix
__global__ __launch_bounds__(256) void split_inputs(
    const float* __restrict__ x,  const float* __restrict__ Wq,
    const float* __restrict__ Wk, const float* __restrict__ Wv,
    const float* __restrict__ Wo)
{
    size_t i = (size_t)blockIdx.x * 256 + threadIdx.x;
    float4 f;
    uint16_t *dh, *dl;
    size_t o4;
    if (i < NX4) {
        f = ((const float4*)x)[i];
        dh = g_xh; dl = g_xl; o4 = i;
    } else {
        size_t j = i - NX4;
        const float* W;
        size_t base;
        if (j < NW4)          { W = Wq; base = 0; }
        else if (j < 2 * NW4) { W = Wk; base = NW4; }
        else if (j < 3 * NW4) { W = Wv; base = 2 * NW4; }
        else                  { W = Wo; base = 3 * NW4; }
        f = ((const float4*)W)[j - base];
        dh = g_wh; dl = g_wl; o4 = j;
    }
    uint32_t h0, l0, h1, l1;
    splitpk(f.x, f.y, h0, l0);
    splitpk(f.z, f.w, h1, l1);
    ((uint32_t*)dh)[o4 * 2]     = h0;
    ((uint32_t*)dh)[o4 * 2 + 1] = h1;
    ((uint32_t*)dl)[o4 * 2]     = l0;
    ((uint32_t*)dl)[o4 * 2 + 1] = l1;
}
#define SPLIT_BLOCKS ((int)((NX4 + 4 * NW4) / 256))   // 4352

// ---------------------------------------------------------------------------
// Warp-level K-chunk compute: 64x32 warp tile, 3-pass split (pass-outermost)
// ---------------------------------------------------------------------------
template<bool TRANSB>
__device__ __forceinline__ void compute_chunk(
    float c[4][4][4],
    const uint16_t* sAhi, const uint16_t* sAlo,
    const uint16_t* sBhi, const uint16_t* sBlo,
    int lane, int mrow0, int ncol0)
{
    const int lr = lane & 7, lg = lane >> 3;
#pragma unroll
    for (int k16 = 0; k16 < 32; k16 += 16) {
        uint32_t ah[4][4], al[4][4];
        uint32_t aoff = (uint32_t)(((mrow0 + (lane & 15)) * AT_STR + k16 + ((lane >> 4) << 3)) * 2);
#pragma unroll
        for (int mi = 0; mi < 4; ++mi) {
            ldmx4(ah[mi], cvta_s(sAhi) + aoff + mi * (16 * AT_STR * 2));
            ldmx4(al[mi], cvta_s(sAlo) + aoff + mi * (16 * AT_STR * 2));
        }
        uint32_t bh[2][4], bl[2][4];
#pragma unroll
        for (int nb = 0; nb < 2; ++nb) {
            uint32_t boff;
            if (TRANSB) {
                boff = (uint32_t)(((k16 + lr + ((lg & 1) << 3)) * BN_STR
                                   + ncol0 + nb * 16 + ((lg & 2) << 2)) * 2);
                ldmx4t(bh[nb], cvta_s(sBhi) + boff);
                ldmx4t(bl[nb], cvta_s(sBlo) + boff);
            } else {
                boff = (uint32_t)(((ncol0 + nb * 16 + lr + ((lg & 2) << 2)) * AT_STR
                                   + k16 + ((lg & 1) << 3)) * 2);
                ldmx4(bh[nb], cvta_s(sBhi) + boff);
                ldmx4(bl[nb], cvta_s(sBlo) + boff);
            }
        }
#pragma unroll
        for (int pass = 0; pass < 3; ++pass)
#pragma unroll
            for (int mi = 0; mi < 4; ++mi)
#pragma unroll
                for (int nb = 0; nb < 2; ++nb)
#pragma unroll
                    for (int half = 0; half < 2; ++half) {
                        float* cc = c[mi][nb * 2 + half];
                        const uint32_t* aa = (pass == 2) ? al[mi] : ah[mi];
                        uint32_t b0 = (pass == 1) ? bl[nb][half * 2]     : bh[nb][half * 2];
                        uint32_t b1 = (pass == 1) ? bl[nb][half * 2 + 1] : bh[nb][half * 2 + 1];
                        mma16816(cc, aa, b0, b1);
                    }
    }
}

// fp32 epilogue
__device__ __forceinline__ void epilogue_store(
    float c[4][4][4], float* __restrict__ C, const float* __restrict__ bias,
    int ldc, int m0, int cn0, int mrow0, int ncol0, int lane)
{
#pragma unroll
    for (int mi = 0; mi < 4; ++mi) {
        int r = m0 + mrow0 + mi * 16 + (lane >> 2);
#pragma unroll
        for (int ni = 0; ni < 4; ++ni) {
            int cl = ncol0 + ni * 8 + ((lane & 3) << 1);
            float b0 = 0.f, b1 = 0.f;
            if (bias) { b0 = bias[cl]; b1 = bias[cl + 1]; }
            float2 v0 = make_float2(c[mi][ni][0] + b0, c[mi][ni][1] + b1);
            float2 v1 = make_float2(c[mi][ni][2] + b0, c[mi][ni][3] + b1);
            *(float2*)(C + (size_t)r * ldc + cn0 + cl) = v0;
            *(float2*)(C + (size_t)(r + 8) * ldc + cn0 + cl) = v1;
        }
    }
}

// bf16 hi/lo split epilogue (generic dst, optional bias indexed by cl)
__device__ __forceinline__ void epilogue_split_g(
    float c[4][4][4], uint16_t* __restrict__ dh, uint16_t* __restrict__ dl,
    const float* __restrict__ bias, int ldc, int m0, int cn0,
    int mrow0, int ncol0, int lane)
{
#pragma unroll
    for (int mi = 0; mi < 4; ++mi) {
        int r = m0 + mrow0 + mi * 16 + (lane >> 2);
#pragma unroll
        for (int ni = 0; ni < 4; ++ni) {
            int cl = ncol0 + ni * 8 + ((lane & 3) << 1);
            float b0 = bias ? bias[cl] : 0.f, b1 = bias ? bias[cl + 1] : 0.f;
            uint32_t h0, l0, h1, l1;
            splitpk(c[mi][ni][0] + b0, c[mi][ni][1] + b1, h0, l0);
            splitpk(c[mi][ni][2] + b0, c[mi][ni][3] + b1, h1, l1);
            size_t o0 = (size_t)r * ldc + cn0 + cl;
            size_t o1 = (size_t)(r + 8) * ldc + cn0 + cl;
            *(uint32_t*)(dh + o0) = h0;
            *(uint32_t*)(dl + o0) = l0;
            *(uint32_t*)(dh + o1) = h1;
            *(uint32_t*)(dl + o1) = l1;
        }
    }
}

// ---------------------------------------------------------------------------
// cp.async stage issuers (pure copies of pre-split bf16)
// ---------------------------------------------------------------------------
__device__ __forceinline__ void issue_tn_cpa(
    uint32_t sbuf, const uint16_t* __restrict__ Ah, const uint16_t* __restrict__ Al,
    const uint16_t* __restrict__ Bh, const uint16_t* __restrict__ Bl,
    int lda, int ldb, int m0, int k0, int tid)
{
#pragma unroll
    for (int j = 0; j < 2; ++j) {
        int u = tid * 2 + j;
        int row = u >> 2, seg = (u & 3) * 8;
        uint32_t off = (uint32_t)((row * AT_STR + seg) * 2);
        size_t ga = (size_t)(m0 + row) * lda + k0 + seg;
        size_t gb = (size_t)row * ldb + k0 + seg;
        cpa16(sbuf + off,          Ah + ga);
        cpa16(sbuf + 10240 + off,  Al + ga);
        cpa16(sbuf + 20480 + off,  Bh + gb);
        cpa16(sbuf + 30720 + off,  Bl + gb);
    }
}

__device__ __forceinline__ void issue_nn_cpa(
    uint32_t sbuf, const uint16_t* __restrict__ Ah, const uint16_t* __restrict__ Al,
    const uint16_t* __restrict__ Bh, const uint16_t* __restrict__ Bl,
    int lda, int ldb, int m0, int n0, int k0, int tid)
{
#pragma unroll
    for (int j = 0; j < 2; ++j) {
        int u = tid * 2 + j;
        int row = u >> 2, seg = (u & 3) * 8;
        uint32_t offa = (uint32_t)((row * AT_STR + seg) * 2);
        size_t ga = (size_t)(m0 + row) * lda + k0 + seg;
        cpa16(sbuf + offa,         Ah + ga);
        cpa16(sbuf + 10240 + offa, Al + ga);
        int kr = u >> 4, sn = (u & 15) * 8;
        uint32_t offb = (uint32_t)((kr * BN_STR + sn) * 2);
        size_t gb = (size_t)(k0 + kr) * ldb + n0 + sn;
        cpa16(sbuf + 20480 + offb,        Bh + gb);
        cpa16(sbuf + 20480 + 8704 + offb, Bl + gb);
    }
}

// ---------------------------------------------------------------------------
// TN GEMM body (cp.async ring, 256 threads, 8 warps 2x4)
// ---------------------------------------------------------------------------
__device__ __forceinline__ void gemm_tn_cpa_body(
    char* sm, float c[4][4][4],
    const uint16_t* Ah, const uint16_t* Al,
    const uint16_t* Bh, const uint16_t* Bl,
    int K, int lda, int ldb, int m0, int lane, int mrow0, int ncol0)
{
    const int tid = threadIdx.x;
    uint32_t sb = cvta_s(sm);
    issue_tn_cpa(sb, Ah, Al, Bh, Bl, lda, ldb, m0, 0, tid);
    CPA_COMMIT();
    int ib = 0;
    for (int k0 = 0; k0 < K; k0 += 32, ib ^= 1) {
        CPA_WAIT0();
        __syncthreads();
        if (k0 + 32 < K) {
            issue_tn_cpa(sb + (ib ^ 1) * TN_BUF_B, Ah, Al, Bh, Bl, lda, ldb, m0, k0 + 32, tid);
            CPA_COMMIT();
        }
        uint16_t* cur = (uint16_t*)(sm + ib * TN_BUF_B);
        compute_chunk<false>(c, cur, cur + 5120, cur + 10240, cur + 15360,
                             lane, mrow0, ncol0);
    }
}

// QKV projection: z 0..5 selects 128-col slab of [q|k|v]; all operands pre-split
__global__ __launch_bounds__(256) void mma_qkv(
    const float* __restrict__ bq, const float* __restrict__ bk,
    const float* __restrict__ bv)
{
    extern __shared__ __align__(16) char sm[];
    const int tid = threadIdx.x, lane = tid & 31, warp = tid >> 5;
    const int mrow0 = (warp & 1) * 64, ncol0 = (warp >> 1) * 32;
    const int z = blockIdx.x;
    const int m0 = blockIdx.y * 128;

    const uint16_t* Bh = g_wh + (size_t)z * 128 * 256;
    const uint16_t* Bl = g_wl + (size_t)z * 128 * 256;

    float c[4][4][4];
#pragma unroll
    for (int i = 0; i < 4; ++i)
#pragma unroll
        for (int j = 0; j < 4; ++j)
#pragma unroll
            for (int q = 0; q < 4; ++q) c[i][j][q] = 0.f;

    gemm_tn_cpa_body(sm, c, g_xh, g_xl, Bh, Bl, 256, 256, 256, m0,
                     lane, mrow0, ncol0);

    if (z < 2)
        epilogue_split_g(c, g_qkh, g_qkl, bq + z * 128, 512, m0, z * 128,
                         mrow0, ncol0, lane);
    else if (z < 4)
        epilogue_split_g(c, g_qkh, g_qkl, bk + (z - 2) * 128, 512, m0, z * 128,
                         mrow0, ncol0, lane);
    else
        epilogue_split_g(c, g_vh, g_vl, bv + (z - 4) * 128, 256, m0, (z - 4) * 128,
                         mrow0, ncol0, lane);
}

// out = tmp @ Wo^T + bo (slabs 6,7 of g_wh)
__global__ __launch_bounds__(256) void mma_out(
    const float* __restrict__ bo, float* __restrict__ out)
{
    extern __shared__ __align__(16) char sm[];
    const int tid = threadIdx.x, lane = tid & 31, warp = tid >> 5;
    const int mrow0 = (warp & 1) * 64, ncol0 = (warp >> 1) * 32;
    const int n0 = blockIdx.x * 128;
    const int m0 = blockIdx.y * 128;

    const uint16_t* Bh = g_wh + (size_t)(6 + blockIdx.x) * 128 * 256;
    const uint16_t* Bl = g_wl + (size_t)(6 + blockIdx.x) * 128 * 256;

    float c[4][4][4];
#pragma unroll
    for (int i = 0; i < 4; ++i)
#pragma unroll
        for (int j = 0; j < 4; ++j)
#pragma unroll
            for (int q = 0; q < 4; ++q) c[i][j][q] = 0.f;

    gemm_tn_cpa_body(sm, c, g_tmph, g_tmpl, Bh, Bl, 256, 256, 256, m0,
                     lane, mrow0, ncol0);
    epilogue_store(c, out, bo + n0, 256, m0, n0, mrow0, ncol0, lane);
}

// NN batched: tmp[b] = avg[b] @ v[b]  (both pre-split), emit tmp pre-split
__global__ __launch_bounds__(256) void mma_nn()
{
    extern __shared__ __align__(16) char sm[];
    const int tid = threadIdx.x, lane = tid & 31, warp = tid >> 5;
    const int mrow0 = (warp & 1) * 64, ncol0 = (warp >> 1) * 32;
    const int n0 = blockIdx.x * 128;
    const int m0 = blockIdx.y * 128;
    const int b  = blockIdx.z;

    const uint16_t* Ah = g_avgh + (size_t)b * 512 * 512;
    const uint16_t* Al = g_avgl + (size_t)b * 512 * 512;
    const uint16_t* Bh = g_vh + (size_t)b * 512 * 256;
    const uint16_t* Bl = g_vl + (size_t)b * 512 * 256;

    float c[4][4][4];
#pragma unroll
    for (int i = 0; i < 4; ++i)
#pragma unroll
        for (int j = 0; j < 4; ++j)
#pragma unroll
            for (int q = 0; q < 4; ++q) c[i][j][q] = 0.f;

    uint32_t sb = cvta_s(sm);
    issue_nn_cpa(sb, Ah, Al, Bh, Bl, 512, 256, m0, n0, 0, tid);
    CPA_COMMIT();
    int ib = 0;
    for (int k0 = 0; k0 < 512; k0 += 32, ib ^= 1) {
        CPA_WAIT0();
        __syncthreads();
        if (k0 + 32 < 512) {
            issue_nn_cpa(sb + (ib ^ 1) * NN_BUF_B, Ah, Al, Bh, Bl,
                         512, 256, m0, n0, k0 + 32, tid);
            CPA_COMMIT();
        }
        uint16_t* cur = (uint16_t*)(sm + ib * NN_BUF_B);
        compute_chunk<true>(c, cur, cur + 5120, cur + 10240, cur + 10240 + 4352,
                            lane, mrow0, ncol0);
    }
    epilogue_split_g(c, g_tmph, g_tmpl, nullptr, 256, b * 512 + m0, n0,
                     mrow0, ncol0, lane);
}

// ---------------------------------------------------------------------------
// Attention v5 (cp.async pipelined) + avg bf16-split side output.
// ---------------------------------------------------------------------------
#define SC_STR 522
#define AQ_H  40960
#define AQ_L  43520
#define ASC   46080
#define ATTN_SMEM_BYTES (46080 + 32 * SC_STR * 4)   // 112896

__global__ __launch_bounds__(512, 2) void attn_sparsemax_kernel(float* __restrict__ avg)
{
    extern __shared__ __align__(16) char sm[];
    float* Ssc = (float*)(sm + ASC);

    const int tid  = threadIdx.x;
    const int lane = tid & 31, w = tid >> 5;
    const int b    = blockIdx.x >> 4;
    const int s0   = (blockIdx.x & 15) << 5;

    const uint16_t* qkh = g_qkh + (size_t)b * 512 * 512;
    const uint16_t* qkl = g_qkl + (size_t)b * 512 * 512;

    float acc[2][16];
#pragma unroll
    for (int qi = 0; qi < 2; ++qi)
#pragma unroll
        for (int i = 0; i < 16; ++i) acc[qi][i] = 0.f;

    auto issue_K = [&](int h, int ck, int ring) {
        int rrow = tid >> 2, seg = (tid & 3) * 8;
        int key = ck * 128 + rrow;
        size_t gofs = (size_t)key * 512 + 256 + h * 32 + seg;
        uint32_t dhi = cvta_s(sm) + (uint32_t)(ring * 20480 + (rrow * AT_STR + seg) * 2);
        cpa16(dhi,         qkh + gofs);
        cpa16(dhi + 10240, qkl + gofs);
    };
    auto issue_Q = [&](int h) {
        if (tid < 256) {
            int u = tid & 127;
            int rrow = u >> 2, seg = (u & 3) * 8;
            const uint16_t* src = (tid < 128) ? qkh : qkl;
            uint32_t dst = cvta_s(sm) + (uint32_t)((tid < 128 ? AQ_H : AQ_L)
                                                   + (rrow * AT_STR + seg) * 2);
            cpa16(dst, src + (size_t)(s0 + rrow) * 512 + h * 32 + seg);
        }
    };

    issue_Q(0);
    issue_K(0, 0, 0);
    CPA_COMMIT();

    for (int h = 0; h < HH; ++h) {
#pragma unroll
        for (int ck = 0; ck < 4; ++ck) {
            const int stage = h * 4 + ck;
            const int ring = stage & 1;
            CPA_WAIT0();
            __syncthreads();
            if (ck < 3) {
                issue_K(h, ck + 1, (stage + 1) & 1);
                CPA_COMMIT();
            }

            const uint32_t kh_base = cvta_s(sm) + (uint32_t)(ring * 20480);
            const uint32_t kl_base = kh_base + 10240;
            const uint32_t qh_base = cvta_s(sm) + AQ_H;
            const uint32_t ql_base = cvta_s(sm) + AQ_L;

            float sc[2][4];
#pragma unroll
            for (int mi = 0; mi < 2; ++mi)
#pragma unroll
                for (int q = 0; q < 4; ++q) sc[mi][q] = 0.f;

#pragma unroll
            for (int k16 = 0; k16 < 32; k16 += 16) {
                uint32_t aoff = (uint32_t)(((lane & 15) * AT_STR + k16 + ((lane >> 4) << 3)) * 2);
                uint32_t ah0[4], ah1[4], al0[4], al1[4];
                ldmx4(ah0, qh_base + aoff);
                ldmx4(ah1, qh_base + aoff + 16 * AT_STR * 2);
                ldmx4(al0, ql_base + aoff);
                ldmx4(al1, ql_base + aoff + 16 * AT_STR * 2);

                int l16 = lane & 15;
                uint32_t boff = (uint32_t)(((w * 8 + (l16 & 7)) * AT_STR
                                            + k16 + ((l16 >> 3) << 3)) * 2);
                uint32_t bh[2], bl[2];
                ldmx2(bh, kh_base + boff);
                ldmx2(bl, kl_base + boff);

                mma16816(sc[0], ah0, bh[0], bh[1]);
                mma16816(sc[1], ah1, bh[0], bh[1]);
                mma16816(sc[0], ah0, bl[0], bl[1]);
                mma16816(sc[1], ah1, bl[0], bl[1]);
                mma16816(sc[0], al0, bh[0], bh[1]);
                mma16816(sc[1], al1, bh[0], bh[1]);
            }

#pragma unroll
            for (int mi = 0; mi < 2; ++mi) {
                int gc = ck * 128 + w * 8 + ((lane & 3) << 1);
                int r0 = mi * 16 + (lane >> 2);
                int r1 = r0 + 8;
                float v0 = sc[mi][0] * 0.17677669529663687f;
                float v1 = sc[mi][1] * 0.17677669529663687f;
                float v2 = sc[mi][2] * 0.17677669529663687f;
                float v3 = sc[mi][3] * 0.17677669529663687f;
                if (gc     == s0 + r0) v0 = -CUDART_INF_F;
                if (gc + 1 == s0 + r0) v1 = -CUDART_INF_F;
                if (gc     == s0 + r1) v2 = -CUDART_INF_F;
                if (gc + 1 == s0 + r1) v3 = -CUDART_INF_F;
                *(float2*)&Ssc[r0 * SC_STR + gc] = make_float2(v0, v1);
                *(float2*)&Ssc[r1 * SC_STR + gc] = make_float2(v2, v3);
            }
        }

        __syncthreads();
        if (h < HH - 1) {
            issue_Q(h + 1);
            issue_K(h + 1, 0, (h * 4 + 4) & 1);
            CPA_COMMIT();
        }

        float zz0[16], zz1[16];
        {
            int q0 = w * 2, q1 = w * 2 + 1;
#pragma unroll
            for (int i = 0; i < 16; ++i) {
                zz0[i] = Ssc[q0 * SC_STR + lane + 32 * i];
                zz1[i] = Ssc[q1 * SC_STR + lane + 32 * i];
            }
        }
        float m0v = -CUDART_INF_F, m1v = -CUDART_INF_F;
#pragma unroll
        for (int i = 0; i < 16; ++i) {
            m0v = fmaxf(m0v, zz0[i]);
            m1v = fmaxf(m1v, zz1[i]);
        }
#pragma unroll
        for (int o = 16; o; o >>= 1) {
            m0v = fmaxf(m0v, __shfl_xor_sync(0xffffffffu, m0v, o));
            m1v = fmaxf(m1v, __shfl_xor_sync(0xffffffffu, m1v, o));
        }
        float tau0 = m0v - 1.0f, tau1 = m1v - 1.0f;
        int prev0 = -1, prev1 = -1;
        bool done0 = false, done1 = false;
        for (int it = 0; it < 64; ++it) {
            float sa0 = 0.f, sa1 = 0.f;
            int ca0 = 0, ca1 = 0;
#pragma unroll
            for (int i = 0; i < 16; ++i) {
                if (zz0[i] > tau0) { sa0 += zz0[i]; ca0++; }
                if (zz1[i] > tau1) { sa1 += zz1[i]; ca1++; }
            }
#pragma unroll
            for (int o = 16; o; o >>= 1) {
                sa0 += __shfl_xor_sync(0xffffffffu, sa0, o);
                sa1 += __shfl_xor_sync(0xffffffffu, sa1, o);
            }
            ca0 = __reduce_add_sync(0xffffffffu, ca0);
            ca1 = __reduce_add_sync(0xffffffffu, ca1);
            if (!done0) {
                if (ca0 == prev0 || ca0 == 0) done0 = true;
                else { prev0 = ca0; tau0 = (sa0 - 1.0f) / (float)ca0; }
            }
            if (!done1) {
                if (ca1 == prev1 || ca1 == 0) done1 = true;
                else { prev1 = ca1; tau1 = (sa1 - 1.0f) / (float)ca1; }
            }
            if (done0 && done1) break;
        }
#pragma unroll
        for (int i = 0; i < 16; ++i) {
            acc[0][i] += fmaxf(zz0[i] - tau0, 0.f) * 0.125f;
            acc[1][i] += fmaxf(zz1[i] - tau1, 0.f) * 0.125f;
        }
    }

    // ---- write head-averaged rows: fp32 (output) + bf16 split (for mma_nn) ----
#pragma unroll
    for (int qi = 0; qi < 2; ++qi) {
        size_t rbase = (size_t)(b * 512 + s0 + w * 2 + qi) * 512;
        float* dst = avg + rbase;
#pragma unroll
        for (int i = 0; i < 16; ++i) {
            float v = acc[qi][i];
            dst[lane + 32 * i] = v;
            uint16_t h, l;
            split1(v, h, l);
            g_avgh[rbase + lane + 32 * i] = h;
            g_avgl[rbase + lane + 32 * i] = l;
        }
    }
}

// ---------------------------------------------------------------------------
extern "C" void kernel_launch(void* const* d_in, const int* in_sizes, int n_in,
                              void* d_out, int out_size)
{
    const float* x  = (const float*)d_in[0];
    const float* Wq = (const float*)d_in[1];
    const float* bq = (const float*)d_in[2];
    const float* Wk = (const float*)d_in[3];
    const float* bk = (const float*)d_in[4];
    const float* Wv = (const float*)d_in[5];
    const float* bv = (const float*)d_in[6];
    const float* Wo = (const float*)d_in[7];
    const float* bo = (const float*)d_in[8];

    float* out = (float*)d_out;                        // [32,512,256]
    float* avg = out + (size_t)NROWS * DD;             // [32,512,512]

    cudaFuncSetAttribute(mma_qkv, cudaFuncAttributeMaxDynamicSharedMemorySize, TN_SMEM_B);
    cudaFuncSetAttribute(mma_out, cudaFuncAttributeMaxDynamicSharedMemorySize, TN_SMEM_B);
    cudaFuncSetAttribute(mma_nn,  cudaFuncAttributeMaxDynamicSharedMemorySize, NN_SMEM_B);
    cudaFuncSetAttribute(attn_sparsemax_kernel,
                         cudaFuncAttributeMaxDynamicSharedMemorySize, ATTN_SMEM_BYTES);

    // 0) pre-split x and weights to bf16 hi/lo
    split_inputs<<<SPLIT_BLOCKS, 256>>>(x, Wq, Wk, Wv, Wo);

    // 1) QKV projections (pure-copy cp.async staging): q,k -> g_qk*, v -> g_v*
    {
        dim3 grid(6, 128);
        mma_qkv<<<grid, 256, TN_SMEM_B>>>(bq, bk, bv);
    }

    // 2) scores (HMMA, cp.async) + sparsemax + head avg -> d_out + g_avg*
    attn_sparsemax_kernel<<<NROWS / 32, 512, ATTN_SMEM_BYTES>>>(avg);

    // 3) tmp[b] = avg[b] @ v[b] -> g_tmp* (pre-split)
    {
        dim3 grid(2, 4, BB);
        mma_nn<<<grid, 256, NN_SMEM_B>>>();
    }

    // 4) out = tmp @ Wo^T + bo
    {
        dim3 grid(2, 128);
        mma_out<<<grid, 256, TN_SMEM_B>>>(bo, out);
    }
}